// round 3
// baseline (speedup 1.0000x reference)
#include <cuda_runtime.h>
#include <cstddef>

typedef unsigned long long ull;

#define HEADS 24
#define HD 128
#define DIMN 3072
#define S_IMG 2048
#define S_TXT 256
#define SEQ 2304
#define EPSV 1e-6f
#define SM_SCALE 0.08838834764831845f   /* 1/sqrt(128) */

// ---------------- device scratch (no allocations allowed) ----------------
__device__ float gQ[SEQ * DIMN];
__device__ float gK[SEQ * DIMN];
__device__ float gV[SEQ * DIMN];
__device__ float gO[SEQ * DIMN];

// ---------------- packed f32x2 helpers (sm_103a FFMA2 path) ----------------
__device__ __forceinline__ ull pk2(float lo, float hi) {
    ull r;
    asm("mov.b64 %0, {%1,%2};" : "=l"(r) : "f"(lo), "f"(hi));
    return r;
}
__device__ __forceinline__ void upk2(ull v, float& lo, float& hi) {
    asm("mov.b64 {%0,%1}, %2;" : "=f"(lo), "=f"(hi) : "l"(v));
}
#define FFMA2(d, a, b) asm("fma.rn.f32x2 %0, %1, %2, %0;" : "+l"(d) : "l"(a), "l"(b))
#define FMUL2(d, a)    asm("mul.rn.f32x2 %0, %0, %1;" : "+l"(d) : "l"(a))

// ---------------- 128x128x(K=3072) fp32 GEMM tile body ----------------
// C[m0:128, n0:128] = A @ B + bias.  A row-major [M, 3072], B row-major [3072, 3072].
// GATHER: A rows come from concat(hidden[2048], encoder[256]).
template <bool GATHER>
__device__ __forceinline__ void gemm_body(const float* __restrict__ A0,
                                          const float* __restrict__ A1,
                                          const float* __restrict__ B,
                                          const float* __restrict__ bias,
                                          float* __restrict__ C,
                                          int m0, int n0)
{
    __shared__ float As[16][128];   // transposed: As[k][m]
    __shared__ float Bs[16][128];   // Bs[k][n]
    const int tid = threadIdx.x;
    const int tx = tid & 15, ty = tid >> 4;

    ull acc[8][4];
#pragma unroll
    for (int i = 0; i < 8; i++)
#pragma unroll
        for (int j = 0; j < 4; j++) acc[i][j] = 0ull;

    for (int k0 = 0; k0 < DIMN; k0 += 16) {
        // load A tile (128 rows x 16 cols), store transposed
#pragma unroll
        for (int i = 0; i < 2; i++) {
            int f = tid + i * 256;
            int row = f >> 2, cg = (f & 3) * 4;
            int m = m0 + row;
            const float* ap;
            if (GATHER)
                ap = (m < S_IMG) ? (A0 + (size_t)m * DIMN)
                                 : (A1 + (size_t)(m - S_IMG) * DIMN);
            else
                ap = A0 + (size_t)m * DIMN;
            float4 v = *(const float4*)(ap + k0 + cg);
            As[cg + 0][row] = v.x;
            As[cg + 1][row] = v.y;
            As[cg + 2][row] = v.z;
            As[cg + 3][row] = v.w;
        }
        // load B tile (16 rows x 128 cols)
#pragma unroll
        for (int i = 0; i < 2; i++) {
            int f = tid + i * 256;
            int row = f >> 5, c4 = (f & 31) * 4;
            *(float4*)&Bs[row][c4] =
                *(const float4*)(B + (size_t)(k0 + row) * DIMN + n0 + c4);
        }
        __syncthreads();
#pragma unroll
        for (int kk = 0; kk < 16; kk++) {
            float4 a0 = *(const float4*)&As[kk][ty * 8];
            float4 a1 = *(const float4*)&As[kk][ty * 8 + 4];
            float4 b0 = *(const float4*)&Bs[kk][tx * 8];
            float4 b1 = *(const float4*)&Bs[kk][tx * 8 + 4];
            ull bp[4] = { pk2(b0.x, b0.y), pk2(b0.z, b0.w),
                          pk2(b1.x, b1.y), pk2(b1.z, b1.w) };
            float av[8] = { a0.x, a0.y, a0.z, a0.w, a1.x, a1.y, a1.z, a1.w };
#pragma unroll
            for (int i = 0; i < 8; i++) {
                ull ad = pk2(av[i], av[i]);
#pragma unroll
                for (int j = 0; j < 4; j++) FFMA2(acc[i][j], ad, bp[j]);
            }
        }
        __syncthreads();
    }
    // epilogue: + bias, store
#pragma unroll
    for (int i = 0; i < 8; i++) {
        float out[8];
#pragma unroll
        for (int j = 0; j < 4; j++) {
            float lo, hi;
            upk2(acc[i][j], lo, hi);
            out[2 * j] = lo;
            out[2 * j + 1] = hi;
        }
        int n = n0 + tx * 8;
#pragma unroll
        for (int j = 0; j < 8; j++) out[j] += bias[n + j];
        float* crow = C + (size_t)(m0 + ty * 8 + i) * DIMN + n;
        *(float4*)crow = make_float4(out[0], out[1], out[2], out[3]);
        *(float4*)(crow + 4) = make_float4(out[4], out[5], out[6], out[7]);
    }
}

__global__ __launch_bounds__(256, 2) void qkv_gemm(
    const float* __restrict__ hs, const float* __restrict__ enc,
    const float* __restrict__ wq, const float* __restrict__ wk,
    const float* __restrict__ wv, const float* __restrict__ bq,
    const float* __restrict__ bk, const float* __restrict__ bv)
{
    int z = blockIdx.z;
    const float* B    = (z == 0) ? wq : ((z == 1) ? wk : wv);
    const float* bias = (z == 0) ? bq : ((z == 1) ? bk : bv);
    float* C          = (z == 0) ? gQ : ((z == 1) ? gK : gV);
    gemm_body<true>(hs, enc, B, bias, C, blockIdx.y * 128, blockIdx.x * 128);
}

__global__ __launch_bounds__(256, 2) void o_gemm(
    const float* __restrict__ wo, const float* __restrict__ bo,
    float* __restrict__ out)
{
    gemm_body<false>(gO, nullptr, wo, bo, out, blockIdx.y * 128, blockIdx.x * 128);
}

// ---------------- fused RMSNorm + RoPE on Q,K ----------------
__global__ __launch_bounds__(128) void norm_rope_kernel(
    const float* __restrict__ nq, const float* __restrict__ nk,
    const float* __restrict__ cosb, const float* __restrict__ sinb)
{
    int s = blockIdx.x, h = blockIdx.y, d = threadIdx.x;
    size_t idx = (size_t)s * DIMN + h * HD + d;
    float q = gQ[idx], k = gK[idx];
    float sq = q * q, sk = k * k;
#pragma unroll
    for (int off = 16; off; off >>= 1) {
        sq += __shfl_xor_sync(0xffffffffu, sq, off);
        sk += __shfl_xor_sync(0xffffffffu, sk, off);
    }
    __shared__ float red[8];
    int w = d >> 5;
    if ((d & 31) == 0) { red[w] = sq; red[4 + w] = sk; }
    __syncthreads();
    float tq = red[0] + red[1] + red[2] + red[3];
    float tk = red[4] + red[5] + red[6] + red[7];
    float rq = rsqrtf(tq * (1.0f / HD) + EPSV);
    float rk = rsqrtf(tk * (1.0f / HD) + EPSV);
    q *= rq * nq[d];
    k *= rk * nk[d];
    if (s < S_IMG) {
        float qo = __shfl_xor_sync(0xffffffffu, q, 1);
        float ko = __shfl_xor_sync(0xffffffffu, k, 1);
        float c = cosb[s * HD + d], sn = sinb[s * HD + d];
        float sgn = (d & 1) ? 1.0f : -1.0f;
        q = q * c + sgn * qo * sn;
        k = k * c + sgn * ko * sn;
    }
    gQ[idx] = q;
    gK[idx] = k;
}

// ---------------- flash attention (fp32, FFMA2) ----------------
// grid (36 q-tiles, 24 heads), 256 threads, 64x64 tiles, d=128.
// Smem: Qs [64][128] rowmajor | KV: K-phase [64 kk2][64 c] ull, V-phase [64][128] f32 | Ps [64][68]
__global__ __launch_bounds__(256, 2) void attn_kernel()
{
    extern __shared__ float sm[];
    float* Qs  = sm;                        // 8192 floats
    ull*   KVu = (ull*)(sm + 64 * 128);     // 4096 ull (= 8192 floats)
    float* KVf = sm + 64 * 128;             // alias for V phase
    float* Ps  = sm + 64 * 128 + 64 * 128;  // 64*68 floats

    const int tid = threadIdx.x;
    const int h = blockIdx.y;
    const int q0 = blockIdx.x * 64;

    // load Q tile, pre-scaled by 1/sqrt(d)
#pragma unroll
    for (int i = 0; i < 8; i++) {
        int f = tid + i * 256;
        int r = f >> 5, d4 = (f & 31) * 4;
        float4 v = *(const float4*)(gQ + (size_t)(q0 + r) * DIMN + h * HD + d4);
        v.x *= SM_SCALE; v.y *= SM_SCALE; v.z *= SM_SCALE; v.w *= SM_SCALE;
        *(float4*)&Qs[r * 128 + d4] = v;
    }

    const int si = tid >> 4, sj = tid & 15;       // S-compute map: 4x4 block
    const int r = tid >> 2, cq = tid & 3;         // O map: 1 row x 32 cols
    float m = -1e30f, l = 0.0f;
    ull oacc[16];
#pragma unroll
    for (int j = 0; j < 16; j++) oacc[j] = 0ull;

    for (int t = 0; t < SEQ / 64; t++) {
        int kv0 = t * 64;
        __syncthreads();   // prev PV done: KV and Ps free
        // load K tile into kk-pair-packed layout KVu[kk2][c]
#pragma unroll
        for (int i = 0; i < 8; i++) {
            int f = tid + i * 256;
            int c = f >> 5, d4 = (f & 31) * 4;
            float4 v = *(const float4*)(gK + (size_t)(kv0 + c) * DIMN + h * HD + d4);
            KVu[(d4 >> 1) * 64 + c]       = pk2(v.x, v.y);
            KVu[((d4 >> 1) + 1) * 64 + c] = pk2(v.z, v.w);
        }
        __syncthreads();
        // S = Q K^T : each thread 4x4, FFMA2 over kk pairs (no pack movs)
        ull sacc[4][4];
#pragma unroll
        for (int i = 0; i < 4; i++)
#pragma unroll
            for (int j = 0; j < 4; j++) sacc[i][j] = 0ull;
#pragma unroll 8
        for (int kk2 = 0; kk2 < 64; kk2++) {
            ull qp[4];
#pragma unroll
            for (int i = 0; i < 4; i++)
                qp[i] = *(const ull*)&Qs[(4 * si + i) * 128 + 2 * kk2];
            ulonglong2 k01 = *(const ulonglong2*)&KVu[kk2 * 64 + 4 * sj];
            ulonglong2 k23 = *(const ulonglong2*)&KVu[kk2 * 64 + 4 * sj + 2];
            ull kp[4] = { k01.x, k01.y, k23.x, k23.y };
#pragma unroll
            for (int i = 0; i < 4; i++)
#pragma unroll
                for (int j = 0; j < 4; j++) FFMA2(sacc[i][j], qp[i], kp[j]);
        }
#pragma unroll
        for (int i = 0; i < 4; i++) {
            float o[4];
#pragma unroll
            for (int j = 0; j < 4; j++) {
                float lo, hi;
                upk2(sacc[i][j], lo, hi);
                o[j] = lo + hi;
            }
            *(float4*)&Ps[(4 * si + i) * 68 + 4 * sj] =
                make_float4(o[0], o[1], o[2], o[3]);
        }
        __syncthreads();   // S done (K reads finished), Ps visible
        // load V tile (row-major) — overlaps with softmax below
#pragma unroll
        for (int i = 0; i < 8; i++) {
            int f = tid + i * 256;
            int c = f >> 5, d4 = (f & 31) * 4;
            *(float4*)&KVf[c * 128 + d4] =
                *(const float4*)(gV + (size_t)(kv0 + c) * DIMN + h * HD + d4);
        }
        // online softmax on own row (4 threads/row, 16 cols each)
        {
            float* prow = Ps + r * 68 + cq * 16;
            float mloc = prow[0];
#pragma unroll
            for (int x = 1; x < 16; x++) mloc = fmaxf(mloc, prow[x]);
            mloc = fmaxf(mloc, __shfl_xor_sync(0xffffffffu, mloc, 1));
            mloc = fmaxf(mloc, __shfl_xor_sync(0xffffffffu, mloc, 2));
            float mnew = fmaxf(m, mloc);
            float corr = __expf(m - mnew);
            float ssum = 0.0f;
#pragma unroll
            for (int x = 0; x < 16; x++) {
                float p = __expf(prow[x] - mnew);
                prow[x] = p;
                ssum += p;
            }
            ssum += __shfl_xor_sync(0xffffffffu, ssum, 1);
            ssum += __shfl_xor_sync(0xffffffffu, ssum, 2);
            l = l * corr + ssum;
            m = mnew;
            ull cp = pk2(corr, corr);
#pragma unroll
            for (int j = 0; j < 16; j++) FMUL2(oacc[j], cp);
        }
        __syncthreads();   // V ready + all Ps rows exp'd
        // O += P V
        {
            const float* pr = Ps + r * 68;
            const ulonglong2* vb =
                (const ulonglong2*)((const ull*)KVf + cq * 16);
#pragma unroll 4
            for (int kk = 0; kk < 64; kk++) {
                float p = pr[kk];
                ull pd = pk2(p, p);
                const ulonglong2* vrow = vb + kk * 32;  // 64 ull per V row
#pragma unroll
                for (int jj = 0; jj < 8; jj++) {
                    ulonglong2 vv = vrow[jj];
                    FFMA2(oacc[2 * jj], pd, vv.x);
                    FFMA2(oacc[2 * jj + 1], pd, vv.y);
                }
            }
        }
    }
    // finalize: O /= l, store
    float linv = 1.0f / l;
    float* orow = gO + (size_t)(q0 + r) * DIMN + h * HD + cq * 32;
#pragma unroll
    for (int j = 0; j < 16; j += 2) {
        float a, b, c, d;
        upk2(oacc[j], a, b);
        upk2(oacc[j + 1], c, d);
        *(float4*)(orow + 2 * j) =
            make_float4(a * linv, b * linv, c * linv, d * linv);
    }
}

// ---------------- txt passthrough ----------------
__global__ __launch_bounds__(256) void copy_txt(float* __restrict__ out)
{
    size_t i = (size_t)blockIdx.x * 256 + threadIdx.x;
    out[(size_t)S_IMG * DIMN + i] = gO[(size_t)S_IMG * DIMN + i];
}

// ---------------- launch ----------------
extern "C" void kernel_launch(void* const* d_in, const int* in_sizes, int n_in,
                              void* d_out, int out_size)
{
    const float* hs  = (const float*)d_in[0];
    const float* enc = (const float*)d_in[1];
    const float* cs  = (const float*)d_in[2];
    const float* sn  = (const float*)d_in[3];
    const float* wq  = (const float*)d_in[4];
    const float* bq  = (const float*)d_in[5];
    const float* wk  = (const float*)d_in[6];
    const float* bk  = (const float*)d_in[7];
    const float* wv  = (const float*)d_in[8];
    const float* bv  = (const float*)d_in[9];
    const float* nqw = (const float*)d_in[10];
    const float* nkw = (const float*)d_in[11];
    const float* wo  = (const float*)d_in[12];
    const float* bo  = (const float*)d_in[13];
    float* out = (float*)d_out;

    (void)in_sizes; (void)n_in; (void)out_size;

    qkv_gemm<<<dim3(24, 18, 3), 256>>>(hs, enc, wq, wk, wv, bq, bk, bv);
    norm_rope_kernel<<<dim3(SEQ, HEADS), 128>>>(nqw, nkw, cs, sn);

    const int attn_smem = (64 * 128 + 64 * 128 + 64 * 68) * 4;  // 82944 B
    cudaFuncSetAttribute(attn_kernel,
                         cudaFuncAttributeMaxDynamicSharedMemorySize, attn_smem);
    attn_kernel<<<dim3(SEQ / 64, HEADS), 256, attn_smem>>>();

    o_gemm<<<dim3(24, 16), 256>>>(wo, bo, out);
    copy_txt<<<(S_TXT * DIMN) / 256, 256>>>(out);
}

// round 8
// speedup vs baseline: 5.5949x; 5.5949x over previous
#include <cuda_runtime.h>
#include <cuda_bf16.h>
#include <cstdint>
#include <cstddef>

typedef __nv_bfloat16 bf16;

// tcgen05 is an arch-specific ('a' target) feature. The harness also builds a
// generic compute_103 PTX pass which must not see tcgen05 instructions.
#if defined(__CUDA_ARCH_FEAT_SM103_ALL) || defined(__CUDA_ARCH_FEAT_SM100_ALL) || \
    defined(__CUDA_ARCH_FEAT_SM101_ALL) || defined(__CUDA_ARCH_FEAT_SM110_ALL) || \
    defined(__CUDA_ARCH_SPECIFIC__)
#define HAS_TCGEN05 1
#else
#define HAS_TCGEN05 0
#endif

#define HEADS 24
#define HD 128
#define DIMN 3072
#define S_IMG 2048
#define S_TXT 256
#define SEQ 2304
#define EPSV 1e-6f
#define SM_SCALE 0.08838834764831845f   /* 1/sqrt(128) */

// ================= device scratch arena (static, no runtime allocs) =========
static constexpr size_t SZ_F   = (size_t)SEQ * DIMN * 4;
static constexpr size_t SZ_BF  = (size_t)SEQ * DIMN * 2;
static constexpr size_t SZ_W   = (size_t)DIMN * DIMN * 2;
static constexpr size_t SZ_S   = (size_t)HEADS * SEQ * SEQ * 4;  // 509.6 MB
static constexpr size_t SZ_OB  = (size_t)S_IMG * DIMN * 2;

static constexpr size_t OFF_Q   = 0;
static constexpr size_t OFF_K   = OFF_Q + SZ_F;
static constexpr size_t OFF_V   = OFF_K + SZ_F;
static constexpr size_t OFF_O   = OFF_V + SZ_F;
static constexpr size_t OFF_XH  = OFF_O + SZ_F;
static constexpr size_t OFF_XL  = OFF_XH + SZ_BF;
static constexpr size_t OFF_QH  = OFF_XL + SZ_BF;
static constexpr size_t OFF_QL  = OFF_QH + SZ_BF;
static constexpr size_t OFF_KH  = OFF_QL + SZ_BF;
static constexpr size_t OFF_KL  = OFF_KH + SZ_BF;
static constexpr size_t OFF_VTH = OFF_KL + SZ_BF;
static constexpr size_t OFF_VTL = OFF_VTH + SZ_BF;
static constexpr size_t OFF_OH  = OFF_VTL + SZ_BF;
static constexpr size_t OFF_OL  = OFF_OH + SZ_OB;
static constexpr size_t OFF_W   = OFF_OL + SZ_OB;         // 8 planes: qh,ql,kh,kl,vh,vl,oh,ol
static constexpr size_t OFF_B   = OFF_W + 8 * SZ_W;       // biases bq,bk,bv,bo
static constexpr size_t OFF_S   = OFF_B + 4 * DIMN * 4;   // S fp32; softmax overwrites in place
static constexpr size_t ARENA_TOTAL = OFF_S + SZ_S;       // ~0.92 GB

__device__ __align__(1024) unsigned char gArena[ARENA_TOTAL];

// ================= PTX helpers (sm_103a) ====================================
__device__ __forceinline__ uint32_t smem_u32(const void* p) {
    uint32_t a;
    asm("{ .reg .u64 t; cvta.to.shared.u64 t, %1; cvt.u32.u64 %0, t; }"
        : "=r"(a) : "l"(p));
    return a;
}
__device__ __forceinline__ uint32_t elect_one_pred() {
    uint32_t pred;
    asm volatile("{\n\t.reg .pred p;\n\telect.sync _|p, 0xFFFFFFFF;\n\t"
                 "selp.b32 %0, 1, 0, p;\n\t}" : "=r"(pred));
    return pred;
}
#define MBARRIER_INIT(addr, cnt) \
    asm volatile("mbarrier.init.shared.b64 [%0], %1;" :: "r"((uint32_t)(addr)), "r"((uint32_t)(cnt)) : "memory")
__device__ __forceinline__ void mbarrier_inval(uint32_t a) {
    asm volatile("mbarrier.inval.shared.b64 [%0];" :: "r"(a) : "memory");
}
#define MBARRIER_WAIT_PARITY(mbar_smem_addr, phase_parity) do { \
    uint32_t _mbar = (uint32_t)(mbar_smem_addr); \
    uint32_t _parity = (uint32_t)(phase_parity); \
    uint32_t _done; \
    asm volatile("{\n\t.reg .pred p;\n\t" \
        "mbarrier.try_wait.parity.acquire.cta.shared::cta.b64 p, [%1], %2;\n\t" \
        "selp.b32 %0, 1, 0, p;\n\t}" \
        : "=r"(_done) : "r"(_mbar), "r"(_parity) : "memory"); \
    if (!_done) { \
        asm volatile("{\n\t.reg .pred P1;\n\t" \
            "WAIT_LOOP_%=:\n\t" \
            "mbarrier.try_wait.parity.acquire.cta.shared::cta.b64 P1, [%0], %1, 0x989680;\n\t" \
            "@P1 bra.uni WAIT_DONE_%=;\n\t" \
            "bra.uni WAIT_LOOP_%=;\n\t" \
            "WAIT_DONE_%=:\n\t}" \
            :: "r"(_mbar), "r"(_parity) : "memory"); \
    } \
} while (0)

#define TCGEN05_ALLOC(smem_addr, nCols) \
    asm volatile("tcgen05.alloc.cta_group::1.sync.aligned.shared::cta.b32 [%0], %1;" \
                 :: "r"((uint32_t)(smem_addr)), "r"((uint32_t)(nCols)) : "memory")
#define TCGEN05_DEALLOC(tmem_addr, nCols) \
    asm volatile("tcgen05.dealloc.cta_group::1.sync.aligned.b32 %0, %1;" \
                 :: "r"(tmem_addr), "r"((uint32_t)(nCols)))
#define TCGEN05_RELINQUISH() \
    asm volatile("tcgen05.relinquish_alloc_permit.cta_group::1.sync.aligned;")
#define TCGEN05_COMMIT(mbar) \
    asm volatile("tcgen05.commit.cta_group::1.mbarrier::arrive::one.shared::cluster.b64 [%0];" \
                 :: "r"((uint32_t)(mbar)) : "memory")
#define TCGEN05_WAIT_LD() asm volatile("tcgen05.wait::ld.sync.aligned;" ::: "memory")
#define TCGEN05_FENCE_BEFORE() asm volatile("tcgen05.fence::before_thread_sync;" ::: "memory")
#define TCGEN05_FENCE_AFTER()  asm volatile("tcgen05.fence::after_thread_sync;" ::: "memory")
#define FENCE_PROXY_ASYNC_CTA() asm volatile("fence.proxy.async.shared::cta;" ::: "memory")

#define TCGEN05_LD_32X32B_X32(r, tmem_addr) \
    asm volatile("tcgen05.ld.sync.aligned.32x32b.x32.b32 " \
        "{%0, %1, %2, %3, %4, %5, %6, %7, %8, %9, %10, %11, %12, %13, %14, %15, " \
        " %16, %17, %18, %19, %20, %21, %22, %23, %24, %25, %26, %27, %28, %29, %30, %31}, [%32];" \
        : "=r"((r)[0]),  "=r"((r)[1]),  "=r"((r)[2]),  "=r"((r)[3]), \
          "=r"((r)[4]),  "=r"((r)[5]),  "=r"((r)[6]),  "=r"((r)[7]), \
          "=r"((r)[8]),  "=r"((r)[9]),  "=r"((r)[10]), "=r"((r)[11]), \
          "=r"((r)[12]), "=r"((r)[13]), "=r"((r)[14]), "=r"((r)[15]), \
          "=r"((r)[16]), "=r"((r)[17]), "=r"((r)[18]), "=r"((r)[19]), \
          "=r"((r)[20]), "=r"((r)[21]), "=r"((r)[22]), "=r"((r)[23]), \
          "=r"((r)[24]), "=r"((r)[25]), "=r"((r)[26]), "=r"((r)[27]), \
          "=r"((r)[28]), "=r"((r)[29]), "=r"((r)[30]), "=r"((r)[31]) \
        : "r"(tmem_addr))

// SMEM descriptor: SW128, Blackwell, K-major 128-byte rows, 8-row (1KB) atoms
static constexpr uint64_t SMEM_DESC_BASE_SW128 =
    (2ull << 61) | (1ull << 46) | (64ull << 32) | (1ull << 16);
#define MAKE_SMEM_DESC(a) (SMEM_DESC_BASE_SW128 | ((uint64_t)((a) >> 4) & 0x3FFF))

// SS bf16 MMA, cta_group::1, idesc: F32 accum, BF16 x BF16, M=128, N=128
__device__ __forceinline__ void mma_f16_ss(uint32_t d, uint64_t a_desc, uint64_t b_desc,
                                           uint32_t idesc, uint32_t en) {
    asm volatile("{\n\t.reg .pred p;\n\tsetp.ne.u32 p, %4, 0;\n\t"
                 "tcgen05.mma.cta_group::1.kind::f16 [%0], %1, %2, %3, {%5, %5, %5, %5}, p;\n\t}"
                 :: "r"(d), "l"(a_desc), "l"(b_desc), "r"(idesc), "r"(en), "r"(0u)
                 : "memory");
}

__device__ __forceinline__ void sts128(uint32_t a, uint4 v) {
    asm volatile("st.shared.v4.b32 [%0], {%1, %2, %3, %4};"
                 :: "r"(a), "r"(v.x), "r"(v.y), "r"(v.z), "r"(v.w) : "memory");
}

__device__ __forceinline__ void split2(float x, bf16& h, bf16& l) {
    h = __float2bfloat16_rn(x);
    l = __float2bfloat16_rn(x - __bfloat162float(h));
}

// ================= generic split-bf16 tcgen05 GEMM ==========================
// C[M,N] = (Ah+Al)[M,K] @ (Bh+Bl)[N,K]^T (+bias), fp32 out.
// 128x128 tile/CTA, K in 64-bf16 SW128 chunks, 12 MMAs per chunk (3-term split).
// A/B/bias addressed as byte offsets into gArena; C arena offset or extC.
#define GEMM_IDESC 0x8200490u
#define GEMM_SMEM  (4 * 16384 + 1024)

__global__ __launch_bounds__(128) void gemm_bf16s(
    long long offAh, long long offAl, long long lda, long long sA,
    long long offBh, long long offBl, long long ldb, long long sB,
    long long offC,  long long ldc,  long long sC,
    long long offBias, long long sBias,
    int K, float* __restrict__ extC)
{
#if HAS_TCGEN05
    extern __shared__ char dsm[];
    __shared__ uint32_t s_tmem[2];
    __shared__ __align__(8) unsigned long long s_mbar[1];

    uint32_t dsb = smem_u32(dsm);
    dsb = (dsb + 1023u) & ~1023u;
    const uint32_t sAh = dsb, sAl = dsb + 16384, sBh = dsb + 32768, sBl = dsb + 49152;
    const uint32_t mbar = smem_u32(s_mbar);
    const uint32_t tptr = smem_u32(s_tmem);

    const int tid = threadIdx.x, wid = tid >> 5;
    const long long b = blockIdx.z;
    const long long m0 = (long long)blockIdx.y * 128;
    const long long n0 = (long long)blockIdx.x * 128;

    const bf16* Ah = (const bf16*)(gArena + offAh) + b * sA;
    const bf16* Al = (const bf16*)(gArena + offAl) + b * sA;
    const bf16* Bh = (const bf16*)(gArena + offBh) + b * sB;
    const bf16* Bl = (const bf16*)(gArena + offBl) + b * sB;
    float* C = (extC ? extC : (float*)(gArena + offC)) + b * sC;
    const float* bias = (offBias >= 0)
        ? (const float*)(gArena + offBias) + b * sBias : nullptr;

    if (wid == 0) {
        TCGEN05_ALLOC(tptr, 128);
        TCGEN05_RELINQUISH();          // free the permit so co-resident CTAs alloc too
    }
    if (tid == 0) MBARRIER_INIT(mbar, 1);
    __syncthreads();
    uint32_t tm;
    asm volatile("ld.shared.b32 %0, [%1];" : "=r"(tm) : "r"(tptr));

    // per-thread tile mapping: 8 rows (r0 + 16i), one 16B k-segment
    const int kc = (tid & 7) * 8;       // bf16 element offset in [0,64)
    const int r0 = tid >> 3;            // base row in [0,16)
    uint32_t swoff[8];
#pragma unroll
    for (int i = 0; i < 8; i++) {
        uint32_t bo = (uint32_t)(r0 + 16 * i) * 128u + (uint32_t)kc * 2u;
        swoff[i] = bo ^ ((bo >> 3) & 0x70);
    }
    const uint64_t dAh = MAKE_SMEM_DESC(sAh), dAl = MAKE_SMEM_DESC(sAl);
    const uint64_t dBh = MAKE_SMEM_DESC(sBh), dBl = MAKE_SMEM_DESC(sBl);

    const int nch = K >> 6;
    for (int c = 0; c < nch; c++) {
        if (c) MBARRIER_WAIT_PARITY(mbar, (c - 1) & 1);   // prior MMA done with smem
        const long long k0 = (long long)c * 64 + kc;
#pragma unroll
        for (int i = 0; i < 8; i++) {
            const long long ra = m0 + r0 + 16 * i;
            const long long rb = n0 + r0 + 16 * i;
            uint4 vah = *(const uint4*)(Ah + ra * lda + k0);
            uint4 val = *(const uint4*)(Al + ra * lda + k0);
            uint4 vbh = *(const uint4*)(Bh + rb * ldb + k0);
            uint4 vbl = *(const uint4*)(Bl + rb * ldb + k0);
            sts128(sAh + swoff[i], vah);
            sts128(sAl + swoff[i], val);
            sts128(sBh + swoff[i], vbh);
            sts128(sBl + swoff[i], vbl);
        }
        FENCE_PROXY_ASYNC_CTA();
        __syncthreads();
        if (wid == 0 && elect_one_pred()) {
#pragma unroll
            for (int k = 0; k < 4; k++)
                mma_f16_ss(tm, dAh + k * 2, dBh + k * 2, GEMM_IDESC, (c | k) != 0);
#pragma unroll
            for (int k = 0; k < 4; k++)
                mma_f16_ss(tm, dAh + k * 2, dBl + k * 2, GEMM_IDESC, 1);
#pragma unroll
            for (int k = 0; k < 4; k++)
                mma_f16_ss(tm, dAl + k * 2, dBh + k * 2, GEMM_IDESC, 1);
            TCGEN05_COMMIT(mbar);
        }
    }
    MBARRIER_WAIT_PARITY(mbar, (nch - 1) & 1);
    TCGEN05_FENCE_AFTER();

    // epilogue: each warp reads its 32 M-rows, 128 N-cols of fp32 D
    const long long row = m0 + wid * 32 + (tid & 31);
    float* crow = C + row * ldc + n0;
#pragma unroll
    for (int base = 0; base < 128; base += 32) {
        uint32_t d[32];
        TCGEN05_LD_32X32B_X32(d, tm + base);
        TCGEN05_WAIT_LD();
        float o[32];
#pragma unroll
        for (int j = 0; j < 32; j++) o[j] = __uint_as_float(d[j]);
        if (bias) {
#pragma unroll
            for (int j = 0; j < 32; j++) o[j] += bias[n0 + base + j];
        }
#pragma unroll
        for (int j = 0; j < 32; j += 4)
            *(float4*)(crow + base + j) = make_float4(o[j], o[j + 1], o[j + 2], o[j + 3]);
    }
    TCGEN05_FENCE_BEFORE();
    __syncthreads();
    if (tid == 0) mbarrier_inval(mbar);
    __syncthreads();
    if (wid == 0) TCGEN05_DEALLOC(tm, 128);
#endif  // HAS_TCGEN05
}

// ================= prep / conversion kernels ================================
__global__ __launch_bounds__(256) void convert_x(
    const float* __restrict__ hs, const float* __restrict__ enc)
{
    bf16* Xh = (bf16*)(gArena + OFF_XH);
    bf16* Xl = (bf16*)(gArena + OFF_XL);
    const int s = blockIdx.x;
    const float* src = (s < S_IMG) ? (hs + (size_t)s * DIMN)
                                   : (enc + (size_t)(s - S_IMG) * DIMN);
    const size_t o = (size_t)s * DIMN;
#pragma unroll
    for (int j = 0; j < 12; j++) {
        int c = threadIdx.x + j * 256;
        bf16 h, l;
        split2(src[c], h, l);
        Xh[o + c] = h; Xl[o + c] = l;
    }
}

// W[k][n] (row-major 3072x3072) -> Wt[n][k] split bf16; z selects weight slot
__global__ __launch_bounds__(256) void transpose_w(
    const float* __restrict__ W0, const float* __restrict__ W1,
    const float* __restrict__ W2, const float* __restrict__ W3)
{
    __shared__ float t[32][33];
    const int z = blockIdx.z;
    const float* W = (z == 0) ? W0 : (z == 1) ? W1 : (z == 2) ? W2 : W3;
    bf16* Th = (bf16*)(gArena + OFF_W + (size_t)z * 2 * SZ_W);
    bf16* Tl = (bf16*)(gArena + OFF_W + (size_t)z * 2 * SZ_W + SZ_W);
    const int k0 = blockIdx.x * 32, n0 = blockIdx.y * 32;
    const int tx = threadIdx.x, ty = threadIdx.y;
#pragma unroll
    for (int r = 0; r < 4; r++)
        t[ty + r * 8][tx] = W[(size_t)(k0 + ty + r * 8) * DIMN + n0 + tx];
    __syncthreads();
#pragma unroll
    for (int r = 0; r < 4; r++) {
        int n = n0 + ty + r * 8, k = k0 + tx;
        bf16 h, l;
        split2(t[tx][ty + r * 8], h, l);
        size_t o = (size_t)n * DIMN + k;
        Th[o] = h; Tl[o] = l;
    }
}

// biases -> arena (contiguous bq,bk,bv,bo)
__global__ __launch_bounds__(256) void copy_bias(
    const float* __restrict__ b0, const float* __restrict__ b1,
    const float* __restrict__ b2, const float* __restrict__ b3)
{
    const int z = blockIdx.y;
    const float* src = (z == 0) ? b0 : (z == 1) ? b1 : (z == 2) ? b2 : b3;
    float* dst = (float*)(gArena + OFF_B) + (size_t)z * DIMN;
    int i = blockIdx.x * 256 + threadIdx.x;
    dst[i] = src[i];
}

// fused RMSNorm + RoPE + scale + split-convert on Q,K
__global__ __launch_bounds__(128) void norm_rope_cv(
    const float* __restrict__ nq, const float* __restrict__ nk,
    const float* __restrict__ cosb, const float* __restrict__ sinb)
{
    const float* Qf = (const float*)(gArena + OFF_Q);
    const float* Kf = (const float*)(gArena + OFF_K);
    bf16* Qh = (bf16*)(gArena + OFF_QH); bf16* Ql = (bf16*)(gArena + OFF_QL);
    bf16* Kh = (bf16*)(gArena + OFF_KH); bf16* Kl = (bf16*)(gArena + OFF_KL);

    const int s = blockIdx.x, h = blockIdx.y, d = threadIdx.x;
    const size_t idx = (size_t)s * DIMN + h * HD + d;
    float q = Qf[idx], k = Kf[idx];
    float sq = q * q, sk = k * k;
#pragma unroll
    for (int off = 16; off; off >>= 1) {
        sq += __shfl_xor_sync(0xffffffffu, sq, off);
        sk += __shfl_xor_sync(0xffffffffu, sk, off);
    }
    __shared__ float red[8];
    const int w = d >> 5;
    if ((d & 31) == 0) { red[w] = sq; red[4 + w] = sk; }
    __syncthreads();
    float tq = red[0] + red[1] + red[2] + red[3];
    float tk = red[4] + red[5] + red[6] + red[7];
    q *= rsqrtf(tq * (1.0f / HD) + EPSV) * nq[d];
    k *= rsqrtf(tk * (1.0f / HD) + EPSV) * nk[d];
    if (s < S_IMG) {
        float qo = __shfl_xor_sync(0xffffffffu, q, 1);
        float ko = __shfl_xor_sync(0xffffffffu, k, 1);
        float c = cosb[s * HD + d], sn = sinb[s * HD + d];
        float sgn = (d & 1) ? 1.0f : -1.0f;
        q = q * c + sgn * qo * sn;
        k = k * c + sgn * ko * sn;
    }
    q *= SM_SCALE;                       // fold softmax scale into Q
    bf16 hh, ll;
    split2(q, hh, ll); Qh[idx] = hh; Ql[idx] = ll;
    split2(k, hh, ll); Kh[idx] = hh; Kl[idx] = ll;
}

// V [s][h*128+d] -> Vt [h][d][s] split bf16
__global__ __launch_bounds__(256) void v_transpose()
{
    const float* V = (const float*)(gArena + OFF_V);
    bf16* Th = (bf16*)(gArena + OFF_VTH);
    bf16* Tl = (bf16*)(gArena + OFF_VTL);
    __shared__ float t[32][33];
    const int s0 = blockIdx.x * 32, d0 = blockIdx.y * 32, h = blockIdx.z;
    const int tx = threadIdx.x, ty = threadIdx.y;
#pragma unroll
    for (int r = 0; r < 4; r++)
        t[ty + r * 8][tx] = V[(size_t)(s0 + ty + r * 8) * DIMN + h * HD + d0 + tx];
    __syncthreads();
#pragma unroll
    for (int r = 0; r < 4; r++) {
        int d = d0 + ty + r * 8, s = s0 + tx;
        bf16 hh, ll;
        split2(t[tx][ty + r * 8], hh, ll);
        size_t o = (size_t)h * HD * SEQ + (size_t)d * SEQ + s;
        Th[o] = hh; Tl[o] = ll;
    }
}

// row softmax over S[24*2304][2304], writing split-bf16 P IN PLACE over the
// fp32 row: bytes [0,4608) = Ph row, [4608,9216) = Pl row. Safe because every
// thread's reads of the full row happen before the first __syncthreads.
__global__ __launch_bounds__(256) void softmax_k()
{
    float* Sb = (float*)(gArena + OFF_S);
    const size_t row = blockIdx.x;
    float* sr = Sb + row * SEQ;
    const int tid = threadIdx.x;
    __shared__ float redm[8], reds[8];

    float v[9];
    float mx = -1e30f;
#pragma unroll
    for (int j = 0; j < 9; j++) { v[j] = sr[tid + j * 256]; mx = fmaxf(mx, v[j]); }
#pragma unroll
    for (int off = 16; off; off >>= 1) mx = fmaxf(mx, __shfl_xor_sync(0xffffffffu, mx, off));
    if ((tid & 31) == 0) redm[tid >> 5] = mx;
    __syncthreads();
    mx = redm[0];
#pragma unroll
    for (int i = 1; i < 8; i++) mx = fmaxf(mx, redm[i]);

    float sum = 0.0f;
#pragma unroll
    for (int j = 0; j < 9; j++) { v[j] = __expf(v[j] - mx); sum += v[j]; }
#pragma unroll
    for (int off = 16; off; off >>= 1) sum += __shfl_xor_sync(0xffffffffu, sum, off);
    if ((tid & 31) == 0) reds[tid >> 5] = sum;
    __syncthreads();
    sum = reds[0] + reds[1] + reds[2] + reds[3] + reds[4] + reds[5] + reds[6] + reds[7];
    const float inv = 1.0f / sum;

    bf16* ph = (bf16*)sr;            // first 2304 bf16
    bf16* pl = ph + SEQ;             // next 2304 bf16
#pragma unroll
    for (int j = 0; j < 9; j++) {
        bf16 h, l;
        split2(v[j] * inv, h, l);
        ph[tid + j * 256] = h;
        pl[tid + j * 256] = l;
    }
}

// O fp32 (img rows) -> split bf16 for final projection
__global__ __launch_bounds__(256) void o_convert()
{
    const float* O = (const float*)(gArena + OFF_O);
    bf16* Oh = (bf16*)(gArena + OFF_OH);
    bf16* Ol = (bf16*)(gArena + OFF_OL);
    const size_t o = (size_t)blockIdx.x * DIMN;
#pragma unroll
    for (int j = 0; j < 12; j++) {
        int c = threadIdx.x + j * 256;
        bf16 h, l;
        split2(O[o + c], h, l);
        Oh[o + c] = h; Ol[o + c] = l;
    }
}

__global__ __launch_bounds__(256) void copy_txt(float* __restrict__ out)
{
    const float* O = (const float*)(gArena + OFF_O);
    size_t i = (size_t)blockIdx.x * 256 + threadIdx.x;
    out[(size_t)S_IMG * DIMN + i] = O[(size_t)S_IMG * DIMN + i];
}

// ================= launch ===================================================
extern "C" void kernel_launch(void* const* d_in, const int* in_sizes, int n_in,
                              void* d_out, int out_size)
{
    const float* hs  = (const float*)d_in[0];
    const float* enc = (const float*)d_in[1];
    const float* cs  = (const float*)d_in[2];
    const float* sn  = (const float*)d_in[3];
    const float* wq  = (const float*)d_in[4];
    const float* wk  = (const float*)d_in[6];
    const float* wv  = (const float*)d_in[8];
    const float* nqw = (const float*)d_in[10];
    const float* nkw = (const float*)d_in[11];
    const float* wo  = (const float*)d_in[12];
    float* out = (float*)d_out;
    (void)in_sizes; (void)n_in; (void)out_size;

    cudaFuncSetAttribute(gemm_bf16s,
                         cudaFuncAttributeMaxDynamicSharedMemorySize, GEMM_SMEM);

    const long long E_W  = (long long)DIMN * DIMN;       // elements per weight plane
    const long long E_F  = (long long)SEQ * DIMN;        // elements per fp32 QKV plane

    // 1. input & weight preparation
    convert_x<<<SEQ, 256>>>(hs, enc);
    transpose_w<<<dim3(DIMN / 32, DIMN / 32, 4), dim3(32, 8)>>>(wq, wk, wv, wo);
    copy_bias<<<dim3(DIMN / 256, 4), 256>>>(
        (const float*)d_in[5], (const float*)d_in[7],
        (const float*)d_in[9], (const float*)d_in[13]);

    // 2. QKV projections, merged: z in {Q,K,V}  (M=2304, N=3072, K=3072)
    gemm_bf16s<<<dim3(24, 18, 3), 128, GEMM_SMEM>>>(
        OFF_XH, OFF_XL, DIMN, 0,
        OFF_W, OFF_W + SZ_W, DIMN, 2 * E_W,
        OFF_Q, DIMN, E_F,
        OFF_B, DIMN, DIMN, nullptr);

    // 3. RMSNorm + RoPE + split-convert; V transpose
    norm_rope_cv<<<dim3(SEQ, HEADS), 128>>>(nqw, nkw, cs, sn);
    v_transpose<<<dim3(SEQ / 32, HD / 32, HEADS), dim3(32, 8)>>>();

    // 4. S = Q K^T per head (M=N=2304, K=128, batch=24)
    gemm_bf16s<<<dim3(18, 18, HEADS), 128, GEMM_SMEM>>>(
        OFF_QH, OFF_QL, DIMN, HD,
        OFF_KH, OFF_KL, DIMN, HD,
        OFF_S, SEQ, (long long)SEQ * SEQ,
        -1, 0, HD, nullptr);

    // 5. softmax rows -> split-bf16 P in place over S
    softmax_k<<<HEADS * SEQ, 256>>>();

    // 6. O = P V per head (M=2304, N=128, K=2304, batch=24)
    //    P rows are 2*SEQ bf16 wide (Ph | Pl per row)
    gemm_bf16s<<<dim3(1, 18, HEADS), 128, GEMM_SMEM>>>(
        OFF_S, OFF_S + (long long)SEQ * 2, 2 * SEQ, (long long)SEQ * 2 * SEQ,
        OFF_VTH, OFF_VTL, SEQ, (long long)HD * SEQ,
        OFF_O, DIMN, HD,
        -1, 0, SEQ, nullptr);

    // 7. output projection on img rows (M=2048, N=3072, K=3072) + txt copy
    o_convert<<<S_IMG, 256>>>();
    gemm_bf16s<<<dim3(24, 16, 1), 128, GEMM_SMEM>>>(
        OFF_OH, OFF_OL, DIMN, 0,
        OFF_W + 6 * SZ_W, OFF_W + 7 * SZ_W, DIMN, 0,
        0, DIMN, 0,
        OFF_B + 3LL * DIMN * 4, 0, DIMN, out);
    copy_txt<<<(S_TXT * DIMN) / 256, 256>>>(out);
}

// round 12
// speedup vs baseline: 9.5838x; 1.7130x over previous
#include <cuda_runtime.h>
#include <cuda_bf16.h>
#include <cstdint>
#include <cstddef>

typedef __nv_bfloat16 bf16;

// tcgen05 is an arch-specific ('a' target) feature. The harness also builds a
// generic compute_103 PTX pass which must not see tcgen05 instructions.
#if defined(__CUDA_ARCH_FEAT_SM103_ALL) || defined(__CUDA_ARCH_FEAT_SM100_ALL) || \
    defined(__CUDA_ARCH_FEAT_SM101_ALL) || defined(__CUDA_ARCH_FEAT_SM110_ALL) || \
    defined(__CUDA_ARCH_SPECIFIC__)
#define HAS_TCGEN05 1
#else
#define HAS_TCGEN05 0
#endif

#define HEADS 24
#define HD 128
#define DIMN 3072
#define S_IMG 2048
#define S_TXT 256
#define SEQ 2304
#define EPSV 1e-6f
#define SM_SCALE 0.08838834764831845f   /* 1/sqrt(128) */

// ================= device scratch arena (static, no runtime allocs) =========
static constexpr size_t SZ_F   = (size_t)SEQ * DIMN * 4;
static constexpr size_t SZ_BF  = (size_t)SEQ * DIMN * 2;
static constexpr size_t SZ_W   = (size_t)DIMN * DIMN * 2;
static constexpr size_t SZ_S   = (size_t)HEADS * SEQ * SEQ * 4;  // 509.6 MB
static constexpr size_t SZ_OB  = (size_t)S_IMG * DIMN * 2;

static constexpr size_t OFF_Q   = 0;
static constexpr size_t OFF_K   = OFF_Q + SZ_F;
static constexpr size_t OFF_V   = OFF_K + SZ_F;
static constexpr size_t OFF_O   = OFF_V + SZ_F;
static constexpr size_t OFF_XH  = OFF_O + SZ_F;
static constexpr size_t OFF_XL  = OFF_XH + SZ_BF;
static constexpr size_t OFF_QH  = OFF_XL + SZ_BF;
static constexpr size_t OFF_QL  = OFF_QH + SZ_BF;
static constexpr size_t OFF_KH  = OFF_QL + SZ_BF;
static constexpr size_t OFF_KL  = OFF_KH + SZ_BF;
static constexpr size_t OFF_VTH = OFF_KL + SZ_BF;
static constexpr size_t OFF_VTL = OFF_VTH + SZ_BF;
static constexpr size_t OFF_OH  = OFF_VTL + SZ_BF;
static constexpr size_t OFF_OL  = OFF_OH + SZ_OB;
static constexpr size_t OFF_W   = OFF_OL + SZ_OB;         // 8 planes: qh,ql,kh,kl,vh,vl,oh,ol
static constexpr size_t OFF_B   = OFF_W + 8 * SZ_W;       // biases bq,bk,bv,bo
static constexpr size_t OFF_S   = OFF_B + 4 * DIMN * 4;   // S fp32; softmax overwrites in place
static constexpr size_t ARENA_TOTAL = OFF_S + SZ_S;       // ~0.92 GB

__device__ __align__(1024) unsigned char gArena[ARENA_TOTAL];

// ================= PTX helpers (sm_103a) ====================================
__device__ __forceinline__ uint32_t smem_u32(const void* p) {
    uint32_t a;
    asm("{ .reg .u64 t; cvta.to.shared.u64 t, %1; cvt.u32.u64 %0, t; }"
        : "=r"(a) : "l"(p));
    return a;
}
__device__ __forceinline__ uint32_t elect_one_pred() {
    uint32_t pred;
    asm volatile("{\n\t.reg .pred p;\n\telect.sync _|p, 0xFFFFFFFF;\n\t"
                 "selp.b32 %0, 1, 0, p;\n\t}" : "=r"(pred));
    return pred;
}
#define MBARRIER_INIT(addr, cnt) \
    asm volatile("mbarrier.init.shared.b64 [%0], %1;" :: "r"((uint32_t)(addr)), "r"((uint32_t)(cnt)) : "memory")
__device__ __forceinline__ void mbarrier_inval(uint32_t a) {
    asm volatile("mbarrier.inval.shared.b64 [%0];" :: "r"(a) : "memory");
}
#define MBARRIER_WAIT_PARITY(mbar_smem_addr, phase_parity) do { \
    uint32_t _mbar = (uint32_t)(mbar_smem_addr); \
    uint32_t _parity = (uint32_t)(phase_parity); \
    uint32_t _done; \
    asm volatile("{\n\t.reg .pred p;\n\t" \
        "mbarrier.try_wait.parity.acquire.cta.shared::cta.b64 p, [%1], %2;\n\t" \
        "selp.b32 %0, 1, 0, p;\n\t}" \
        : "=r"(_done) : "r"(_mbar), "r"(_parity) : "memory"); \
    if (!_done) { \
        asm volatile("{\n\t.reg .pred P1;\n\t" \
            "WAIT_LOOP_%=:\n\t" \
            "mbarrier.try_wait.parity.acquire.cta.shared::cta.b64 P1, [%0], %1, 0x989680;\n\t" \
            "@P1 bra.uni WAIT_DONE_%=;\n\t" \
            "bra.uni WAIT_LOOP_%=;\n\t" \
            "WAIT_DONE_%=:\n\t}" \
            :: "r"(_mbar), "r"(_parity) : "memory"); \
    } \
} while (0)

#define TCGEN05_ALLOC(smem_addr, nCols) \
    asm volatile("tcgen05.alloc.cta_group::1.sync.aligned.shared::cta.b32 [%0], %1;" \
                 :: "r"((uint32_t)(smem_addr)), "r"((uint32_t)(nCols)) : "memory")
#define TCGEN05_DEALLOC(tmem_addr, nCols) \
    asm volatile("tcgen05.dealloc.cta_group::1.sync.aligned.b32 %0, %1;" \
                 :: "r"(tmem_addr), "r"((uint32_t)(nCols)))
#define TCGEN05_RELINQUISH() \
    asm volatile("tcgen05.relinquish_alloc_permit.cta_group::1.sync.aligned;")
#define TCGEN05_COMMIT(mbar) \
    asm volatile("tcgen05.commit.cta_group::1.mbarrier::arrive::one.shared::cluster.b64 [%0];" \
                 :: "r"((uint32_t)(mbar)) : "memory")
#define TCGEN05_WAIT_LD() asm volatile("tcgen05.wait::ld.sync.aligned;" ::: "memory")
#define TCGEN05_FENCE_BEFORE() asm volatile("tcgen05.fence::before_thread_sync;" ::: "memory")
#define TCGEN05_FENCE_AFTER()  asm volatile("tcgen05.fence::after_thread_sync;" ::: "memory")
#define FENCE_PROXY_ASYNC_CTA() asm volatile("fence.proxy.async.shared::cta;" ::: "memory")

// cp.async (LDGSTS) helpers
#define CP_ASYNC16(smem, gptr) \
    asm volatile("cp.async.cg.shared.global [%0], [%1], 16;" \
                 :: "r"((uint32_t)(smem)), "l"(gptr) : "memory")
#define CP_COMMIT() asm volatile("cp.async.commit_group;" ::: "memory")
#define CP_WAIT1()  asm volatile("cp.async.wait_group 1;" ::: "memory")

#define TCGEN05_LD_32X32B_X32(r, tmem_addr) \
    asm volatile("tcgen05.ld.sync.aligned.32x32b.x32.b32 " \
        "{%0, %1, %2, %3, %4, %5, %6, %7, %8, %9, %10, %11, %12, %13, %14, %15, " \
        " %16, %17, %18, %19, %20, %21, %22, %23, %24, %25, %26, %27, %28, %29, %30, %31}, [%32];" \
        : "=r"((r)[0]),  "=r"((r)[1]),  "=r"((r)[2]),  "=r"((r)[3]), \
          "=r"((r)[4]),  "=r"((r)[5]),  "=r"((r)[6]),  "=r"((r)[7]), \
          "=r"((r)[8]),  "=r"((r)[9]),  "=r"((r)[10]), "=r"((r)[11]), \
          "=r"((r)[12]), "=r"((r)[13]), "=r"((r)[14]), "=r"((r)[15]), \
          "=r"((r)[16]), "=r"((r)[17]), "=r"((r)[18]), "=r"((r)[19]), \
          "=r"((r)[20]), "=r"((r)[21]), "=r"((r)[22]), "=r"((r)[23]), \
          "=r"((r)[24]), "=r"((r)[25]), "=r"((r)[26]), "=r"((r)[27]), \
          "=r"((r)[28]), "=r"((r)[29]), "=r"((r)[30]), "=r"((r)[31]) \
        : "r"(tmem_addr))

// SMEM descriptor: SW128, Blackwell, K-major 128-byte rows, 8-row (1KB) atoms
static constexpr uint64_t SMEM_DESC_BASE_SW128 =
    (2ull << 61) | (1ull << 46) | (64ull << 32) | (1ull << 16);
#define MAKE_SMEM_DESC(a) (SMEM_DESC_BASE_SW128 | ((uint64_t)((a) >> 4) & 0x3FFF))

// SS bf16 MMA, cta_group::1, idesc: F32 accum, BF16 x BF16, M=128, N=128
__device__ __forceinline__ void mma_f16_ss(uint32_t d, uint64_t a_desc, uint64_t b_desc,
                                           uint32_t idesc, uint32_t en) {
    asm volatile("{\n\t.reg .pred p;\n\tsetp.ne.u32 p, %4, 0;\n\t"
                 "tcgen05.mma.cta_group::1.kind::f16 [%0], %1, %2, %3, {%5, %5, %5, %5}, p;\n\t}"
                 :: "r"(d), "l"(a_desc), "l"(b_desc), "r"(idesc), "r"(en), "r"(0u)
                 : "memory");
}

__device__ __forceinline__ void split2(float x, bf16& h, bf16& l) {
    h = __float2bfloat16_rn(x);
    l = __float2bfloat16_rn(x - __bfloat162float(h));
}

// ================= generic split-bf16 tcgen05 GEMM (cp.async 2-stage) =======
// C[M,N] = (Ah+Al)[M,K] @ (Bh+Bl)[N,K]^T (+bias), fp32 out.
// 128x128 tile/CTA, K in 64-bf16 SW128 chunks, 12 MMAs/chunk (3-term split).
// 2-stage double buffer: stage = 4 planes x 16KB = 64KB; loads via cp.async.
#define GEMM_IDESC  0x8200490u
#define STAGE_BYTES 65536
#define GEMM_SMEM   (2 * STAGE_BYTES + 1024)

__global__ __launch_bounds__(128) void gemm_bf16s(
    long long offAh, long long offAl, long long lda, long long sA,
    long long offBh, long long offBl, long long ldb, long long sB,
    long long offC,  long long ldc,  long long sC,
    long long offBias, long long sBias,
    int K, float* __restrict__ extC)
{
#if HAS_TCGEN05
    extern __shared__ char dsm[];
    __shared__ uint32_t s_tmem[2];
    __shared__ __align__(8) unsigned long long s_mbar[1];

    uint32_t dsb = smem_u32(dsm);
    dsb = (dsb + 1023u) & ~1023u;
    const uint32_t mbar = smem_u32(s_mbar);
    const uint32_t tptr = smem_u32(s_tmem);

    const int tid = threadIdx.x, wid = tid >> 5;
    const long long b = blockIdx.z;
    const long long m0 = (long long)blockIdx.y * 128;
    const long long n0 = (long long)blockIdx.x * 128;

    const bf16* Ah = (const bf16*)(gArena + offAh) + b * sA;
    const bf16* Al = (const bf16*)(gArena + offAl) + b * sA;
    const bf16* Bh = (const bf16*)(gArena + offBh) + b * sB;
    const bf16* Bl = (const bf16*)(gArena + offBl) + b * sB;
    float* C = (extC ? extC : (float*)(gArena + offC)) + b * sC;
    const float* bias = (offBias >= 0)
        ? (const float*)(gArena + offBias) + b * sBias : nullptr;

    if (wid == 0) {
        TCGEN05_ALLOC(tptr, 128);
        TCGEN05_RELINQUISH();
    }
    if (tid == 0) MBARRIER_INIT(mbar, 1);
    __syncthreads();
    uint32_t tm;
    asm volatile("ld.shared.b32 %0, [%1];" : "=r"(tm) : "r"(tptr));

    // per-thread tile mapping: 8 rows (r0 + 16i), one 16B k-segment
    const int kc = (tid & 7) * 8;       // bf16 element offset in [0,64)
    const int r0 = tid >> 3;            // base row in [0,16)
    uint32_t swoff[8];
    long long rowA[8], rowB[8];
#pragma unroll
    for (int i = 0; i < 8; i++) {
        uint32_t bo = (uint32_t)(r0 + 16 * i) * 128u + (uint32_t)kc * 2u;
        swoff[i] = bo ^ ((bo >> 3) & 0x70);
        rowA[i] = (m0 + r0 + 16 * i) * lda + kc;
        rowB[i] = (n0 + r0 + 16 * i) * ldb + kc;
    }

    const int nch = K >> 6;

    // issue all 32 cp.async for one chunk into one stage
    auto issue_loads = [&](int c, int s) {
        const uint32_t st = dsb + (uint32_t)s * STAGE_BYTES;
        const long long k64 = (long long)c * 64;
#pragma unroll
        for (int i = 0; i < 8; i++) {
            CP_ASYNC16(st +         swoff[i], Ah + rowA[i] + k64);
            CP_ASYNC16(st + 16384 + swoff[i], Al + rowA[i] + k64);
            CP_ASYNC16(st + 32768 + swoff[i], Bh + rowB[i] + k64);
            CP_ASYNC16(st + 49152 + swoff[i], Bl + rowB[i] + k64);
        }
    };

    // prologue: prefetch chunks 0 and 1 (nch >= 2 for all our shapes)
    issue_loads(0, 0); CP_COMMIT();
    issue_loads(1, 1); CP_COMMIT();

    for (int c = 0; c < nch; c++) {
        CP_WAIT1();                       // chunk c resident (c+1 may be in flight)
        FENCE_PROXY_ASYNC_CTA();
        __syncthreads();

        if (wid == 0 && elect_one_pred()) {
            const uint32_t st = dsb + (uint32_t)(c & 1) * STAGE_BYTES;
            const uint64_t dAh = MAKE_SMEM_DESC(st);
            const uint64_t dAl = MAKE_SMEM_DESC(st + 16384);
            const uint64_t dBh = MAKE_SMEM_DESC(st + 32768);
            const uint64_t dBl = MAKE_SMEM_DESC(st + 49152);
#pragma unroll
            for (int k = 0; k < 4; k++)
                mma_f16_ss(tm, dAh + k * 2, dBh + k * 2, GEMM_IDESC, (c | k) != 0);
#pragma unroll
            for (int k = 0; k < 4; k++)
                mma_f16_ss(tm, dAh + k * 2, dBl + k * 2, GEMM_IDESC, 1);
#pragma unroll
            for (int k = 0; k < 4; k++)
                mma_f16_ss(tm, dAl + k * 2, dBh + k * 2, GEMM_IDESC, 1);
            TCGEN05_COMMIT(mbar);
        }
        // MMA(c) must finish before stage (c&1) is refilled with chunk c+2
        MBARRIER_WAIT_PARITY(mbar, c & 1);
        if (c + 2 < nch) issue_loads(c + 2, c & 1);
        CP_COMMIT();                      // keep group counting uniform (may be empty)
    }
    TCGEN05_FENCE_AFTER();

    // epilogue: each warp reads its 32 M-rows, 128 N-cols of fp32 D
    const long long row = m0 + wid * 32 + (tid & 31);
    float* crow = C + row * ldc + n0;
#pragma unroll
    for (int base = 0; base < 128; base += 32) {
        uint32_t d[32];
        TCGEN05_LD_32X32B_X32(d, tm + base);
        TCGEN05_WAIT_LD();
        float o[32];
#pragma unroll
        for (int j = 0; j < 32; j++) o[j] = __uint_as_float(d[j]);
        if (bias) {
#pragma unroll
            for (int j = 0; j < 32; j++) o[j] += bias[n0 + base + j];
        }
#pragma unroll
        for (int j = 0; j < 32; j += 4)
            *(float4*)(crow + base + j) = make_float4(o[j], o[j + 1], o[j + 2], o[j + 3]);
    }
    TCGEN05_FENCE_BEFORE();
    __syncthreads();
    if (tid == 0) mbarrier_inval(mbar);
    __syncthreads();
    if (wid == 0) TCGEN05_DEALLOC(tm, 128);
#endif  // HAS_TCGEN05
}

// ================= prep / conversion kernels ================================
__global__ __launch_bounds__(256) void convert_x(
    const float* __restrict__ hs, const float* __restrict__ enc)
{
    bf16* Xh = (bf16*)(gArena + OFF_XH);
    bf16* Xl = (bf16*)(gArena + OFF_XL);
    const int s = blockIdx.x;
    const float* src = (s < S_IMG) ? (hs + (size_t)s * DIMN)
                                   : (enc + (size_t)(s - S_IMG) * DIMN);
    const size_t o = (size_t)s * DIMN;
#pragma unroll
    for (int j = 0; j < 12; j++) {
        int c = threadIdx.x + j * 256;
        bf16 h, l;
        split2(src[c], h, l);
        Xh[o + c] = h; Xl[o + c] = l;
    }
}

// W[k][n] (row-major 3072x3072) -> Wt[n][k] split bf16; z selects weight slot
__global__ __launch_bounds__(256) void transpose_w(
    const float* __restrict__ W0, const float* __restrict__ W1,
    const float* __restrict__ W2, const float* __restrict__ W3)
{
    __shared__ float t[32][33];
    const int z = blockIdx.z;
    const float* W = (z == 0) ? W0 : (z == 1) ? W1 : (z == 2) ? W2 : W3;
    bf16* Th = (bf16*)(gArena + OFF_W + (size_t)z * 2 * SZ_W);
    bf16* Tl = (bf16*)(gArena + OFF_W + (size_t)z * 2 * SZ_W + SZ_W);
    const int k0 = blockIdx.x * 32, n0 = blockIdx.y * 32;
    const int tx = threadIdx.x, ty = threadIdx.y;
#pragma unroll
    for (int r = 0; r < 4; r++)
        t[ty + r * 8][tx] = W[(size_t)(k0 + ty + r * 8) * DIMN + n0 + tx];
    __syncthreads();
#pragma unroll
    for (int r = 0; r < 4; r++) {
        int n = n0 + ty + r * 8, k = k0 + tx;
        bf16 h, l;
        split2(t[tx][ty + r * 8], h, l);
        size_t o = (size_t)n * DIMN + k;
        Th[o] = h; Tl[o] = l;
    }
}

// biases -> arena (contiguous bq,bk,bv,bo)
__global__ __launch_bounds__(256) void copy_bias(
    const float* __restrict__ b0, const float* __restrict__ b1,
    const float* __restrict__ b2, const float* __restrict__ b3)
{
    const int z = blockIdx.y;
    const float* src = (z == 0) ? b0 : (z == 1) ? b1 : (z == 2) ? b2 : b3;
    float* dst = (float*)(gArena + OFF_B) + (size_t)z * DIMN;
    int i = blockIdx.x * 256 + threadIdx.x;
    dst[i] = src[i];
}

// fused RMSNorm + RoPE + scale + split-convert on Q,K
__global__ __launch_bounds__(128) void norm_rope_cv(
    const float* __restrict__ nq, const float* __restrict__ nk,
    const float* __restrict__ cosb, const float* __restrict__ sinb)
{
    const float* Qf = (const float*)(gArena + OFF_Q);
    const float* Kf = (const float*)(gArena + OFF_K);
    bf16* Qh = (bf16*)(gArena + OFF_QH); bf16* Ql = (bf16*)(gArena + OFF_QL);
    bf16* Kh = (bf16*)(gArena + OFF_KH); bf16* Kl = (bf16*)(gArena + OFF_KL);

    const int s = blockIdx.x, h = blockIdx.y, d = threadIdx.x;
    const size_t idx = (size_t)s * DIMN + h * HD + d;
    float q = Qf[idx], k = Kf[idx];
    float sq = q * q, sk = k * k;
#pragma unroll
    for (int off = 16; off; off >>= 1) {
        sq += __shfl_xor_sync(0xffffffffu, sq, off);
        sk += __shfl_xor_sync(0xffffffffu, sk, off);
    }
    __shared__ float red[8];
    const int w = d >> 5;
    if ((d & 31) == 0) { red[w] = sq; red[4 + w] = sk; }
    __syncthreads();
    float tq = red[0] + red[1] + red[2] + red[3];
    float tk = red[4] + red[5] + red[6] + red[7];
    q *= rsqrtf(tq * (1.0f / HD) + EPSV) * nq[d];
    k *= rsqrtf(tk * (1.0f / HD) + EPSV) * nk[d];
    if (s < S_IMG) {
        float qo = __shfl_xor_sync(0xffffffffu, q, 1);
        float ko = __shfl_xor_sync(0xffffffffu, k, 1);
        float c = cosb[s * HD + d], sn = sinb[s * HD + d];
        float sgn = (d & 1) ? 1.0f : -1.0f;
        q = q * c + sgn * qo * sn;
        k = k * c + sgn * ko * sn;
    }
    q *= SM_SCALE;                       // fold softmax scale into Q
    bf16 hh, ll;
    split2(q, hh, ll); Qh[idx] = hh; Ql[idx] = ll;
    split2(k, hh, ll); Kh[idx] = hh; Kl[idx] = ll;
}

// V [s][h*128+d] -> Vt [h][d][s] split bf16
__global__ __launch_bounds__(256) void v_transpose()
{
    const float* V = (const float*)(gArena + OFF_V);
    bf16* Th = (bf16*)(gArena + OFF_VTH);
    bf16* Tl = (bf16*)(gArena + OFF_VTL);
    __shared__ float t[32][33];
    const int s0 = blockIdx.x * 32, d0 = blockIdx.y * 32, h = blockIdx.z;
    const int tx = threadIdx.x, ty = threadIdx.y;
#pragma unroll
    for (int r = 0; r < 4; r++)
        t[ty + r * 8][tx] = V[(size_t)(s0 + ty + r * 8) * DIMN + h * HD + d0 + tx];
    __syncthreads();
#pragma unroll
    for (int r = 0; r < 4; r++) {
        int d = d0 + ty + r * 8, s = s0 + tx;
        bf16 hh, ll;
        split2(t[tx][ty + r * 8], hh, ll);
        size_t o = (size_t)h * HD * SEQ + (size_t)d * SEQ + s;
        Th[o] = hh; Tl[o] = ll;
    }
}

// row softmax over S[24*2304][2304], writing split-bf16 P IN PLACE over the
// fp32 row: bytes [0,4608) = Ph row, [4608,9216) = Pl row. Safe because every
// thread's reads of the full row happen before the first __syncthreads.
__global__ __launch_bounds__(256) void softmax_k()
{
    float* Sb = (float*)(gArena + OFF_S);
    const size_t row = blockIdx.x;
    float* sr = Sb + row * SEQ;
    const int tid = threadIdx.x;
    __shared__ float redm[8], reds[8];

    float v[9];
    float mx = -1e30f;
#pragma unroll
    for (int j = 0; j < 9; j++) { v[j] = sr[tid + j * 256]; mx = fmaxf(mx, v[j]); }
#pragma unroll
    for (int off = 16; off; off >>= 1) mx = fmaxf(mx, __shfl_xor_sync(0xffffffffu, mx, off));
    if ((tid & 31) == 0) redm[tid >> 5] = mx;
    __syncthreads();
    mx = redm[0];
#pragma unroll
    for (int i = 1; i < 8; i++) mx = fmaxf(mx, redm[i]);

    float sum = 0.0f;
#pragma unroll
    for (int j = 0; j < 9; j++) { v[j] = __expf(v[j] - mx); sum += v[j]; }
#pragma unroll
    for (int off = 16; off; off >>= 1) sum += __shfl_xor_sync(0xffffffffu, sum, off);
    if ((tid & 31) == 0) reds[tid >> 5] = sum;
    __syncthreads();
    sum = reds[0] + reds[1] + reds[2] + reds[3] + reds[4] + reds[5] + reds[6] + reds[7];
    const float inv = 1.0f / sum;

    bf16* ph = (bf16*)sr;            // first 2304 bf16
    bf16* pl = ph + SEQ;             // next 2304 bf16
#pragma unroll
    for (int j = 0; j < 9; j++) {
        bf16 h, l;
        split2(v[j] * inv, h, l);
        ph[tid + j * 256] = h;
        pl[tid + j * 256] = l;
    }
}

// O fp32 (img rows) -> split bf16 for final projection
__global__ __launch_bounds__(256) void o_convert()
{
    const float* O = (const float*)(gArena + OFF_O);
    bf16* Oh = (bf16*)(gArena + OFF_OH);
    bf16* Ol = (bf16*)(gArena + OFF_OL);
    const size_t o = (size_t)blockIdx.x * DIMN;
#pragma unroll
    for (int j = 0; j < 12; j++) {
        int c = threadIdx.x + j * 256;
        bf16 h, l;
        split2(O[o + c], h, l);
        Oh[o + c] = h; Ol[o + c] = l;
    }
}

__global__ __launch_bounds__(256) void copy_txt(float* __restrict__ out)
{
    const float* O = (const float*)(gArena + OFF_O);
    size_t i = (size_t)blockIdx.x * 256 + threadIdx.x;
    out[(size_t)S_IMG * DIMN + i] = O[(size_t)S_IMG * DIMN + i];
}

// ================= launch ===================================================
extern "C" void kernel_launch(void* const* d_in, const int* in_sizes, int n_in,
                              void* d_out, int out_size)
{
    const float* hs  = (const float*)d_in[0];
    const float* enc = (const float*)d_in[1];
    const float* cs  = (const float*)d_in[2];
    const float* sn  = (const float*)d_in[3];
    const float* wq  = (const float*)d_in[4];
    const float* wk  = (const float*)d_in[6];
    const float* wv  = (const float*)d_in[8];
    const float* nqw = (const float*)d_in[10];
    const float* nkw = (const float*)d_in[11];
    const float* wo  = (const float*)d_in[12];
    float* out = (float*)d_out;
    (void)in_sizes; (void)n_in; (void)out_size;

    cudaFuncSetAttribute(gemm_bf16s,
                         cudaFuncAttributeMaxDynamicSharedMemorySize, GEMM_SMEM);

    const long long E_W  = (long long)DIMN * DIMN;       // elements per weight plane
    const long long E_F  = (long long)SEQ * DIMN;        // elements per fp32 QKV plane

    // 1. input & weight preparation
    convert_x<<<SEQ, 256>>>(hs, enc);
    transpose_w<<<dim3(DIMN / 32, DIMN / 32, 4), dim3(32, 8)>>>(wq, wk, wv, wo);
    copy_bias<<<dim3(DIMN / 256, 4), 256>>>(
        (const float*)d_in[5], (const float*)d_in[7],
        (const float*)d_in[9], (const float*)d_in[13]);

    // 2. QKV projections, merged: z in {Q,K,V}  (M=2304, N=3072, K=3072)
    gemm_bf16s<<<dim3(24, 18, 3), 128, GEMM_SMEM>>>(
        OFF_XH, OFF_XL, DIMN, 0,
        OFF_W, OFF_W + SZ_W, DIMN, 2 * E_W,
        OFF_Q, DIMN, E_F,
        OFF_B, DIMN, DIMN, nullptr);

    // 3. RMSNorm + RoPE + split-convert; V transpose
    norm_rope_cv<<<dim3(SEQ, HEADS), 128>>>(nqw, nkw, cs, sn);
    v_transpose<<<dim3(SEQ / 32, HD / 32, HEADS), dim3(32, 8)>>>();

    // 4. S = Q K^T per head (M=N=2304, K=128, batch=24)
    gemm_bf16s<<<dim3(18, 18, HEADS), 128, GEMM_SMEM>>>(
        OFF_QH, OFF_QL, DIMN, HD,
        OFF_KH, OFF_KL, DIMN, HD,
        OFF_S, SEQ, (long long)SEQ * SEQ,
        -1, 0, HD, nullptr);

    // 5. softmax rows -> split-bf16 P in place over S
    softmax_k<<<HEADS * SEQ, 256>>>();

    // 6. O = P V per head (M=2304, N=128, K=2304, batch=24)
    //    P rows are 2*SEQ bf16 wide (Ph | Pl per row)
    gemm_bf16s<<<dim3(1, 18, HEADS), 128, GEMM_SMEM>>>(
        OFF_S, OFF_S + (long long)SEQ * 2, 2 * SEQ, (long long)SEQ * 2 * SEQ,
        OFF_VTH, OFF_VTL, SEQ, (long long)HD * SEQ,
        OFF_O, DIMN, HD,
        -1, 0, SEQ, nullptr);

    // 7. output projection on img rows (M=2048, N=3072, K=3072) + txt copy
    o_convert<<<S_IMG, 256>>>();
    gemm_bf16s<<<dim3(24, 16, 1), 128, GEMM_SMEM>>>(
        OFF_OH, OFF_OL, DIMN, 0,
        OFF_W + 6 * SZ_W, OFF_W + 7 * SZ_W, DIMN, 0,
        0, DIMN, 0,
        OFF_B + 3LL * DIMN * 4, 0, DIMN, out);
    copy_txt<<<(S_TXT * DIMN) / 256, 256>>>(out);
}

// round 15
// speedup vs baseline: 10.2537x; 1.0699x over previous
#include <cuda_runtime.h>
#include <cuda_bf16.h>
#include <cstdint>
#include <cstddef>

typedef __nv_bfloat16 bf16;

// tcgen05 is an arch-specific ('a' target) feature. The harness also builds a
// generic compute_103 PTX pass which must not see tcgen05 instructions.
#if defined(__CUDA_ARCH_FEAT_SM103_ALL) || defined(__CUDA_ARCH_FEAT_SM100_ALL) || \
    defined(__CUDA_ARCH_FEAT_SM101_ALL) || defined(__CUDA_ARCH_FEAT_SM110_ALL) || \
    defined(__CUDA_ARCH_SPECIFIC__)
#define HAS_TCGEN05 1
#else
#define HAS_TCGEN05 0
#endif

#define HEADS 24
#define HD 128
#define DIMN 3072
#define S_IMG 2048
#define S_TXT 256
#define SEQ 2304
#define EPSV 1e-6f
#define SM_SCALE 0.08838834764831845f   /* 1/sqrt(128) */

// ================= device scratch arena (static, no runtime allocs) =========
static constexpr size_t SZ_F   = (size_t)SEQ * DIMN * 4;
static constexpr size_t SZ_BF  = (size_t)SEQ * DIMN * 2;
static constexpr size_t SZ_W   = (size_t)DIMN * DIMN * 2;
static constexpr size_t SZ_S   = (size_t)HEADS * SEQ * SEQ * 4;  // 509.6 MB
static constexpr size_t SZ_OB  = (size_t)S_IMG * DIMN * 2;

static constexpr size_t OFF_Q   = 0;
static constexpr size_t OFF_K   = OFF_Q + SZ_F;
static constexpr size_t OFF_V   = OFF_K + SZ_F;
static constexpr size_t OFF_O   = OFF_V + SZ_F;
static constexpr size_t OFF_XH  = OFF_O + SZ_F;
static constexpr size_t OFF_XL  = OFF_XH + SZ_BF;
static constexpr size_t OFF_QH  = OFF_XL + SZ_BF;
static constexpr size_t OFF_QL  = OFF_QH + SZ_BF;
static constexpr size_t OFF_KH  = OFF_QL + SZ_BF;
static constexpr size_t OFF_KL  = OFF_KH + SZ_BF;
static constexpr size_t OFF_VTH = OFF_KL + SZ_BF;
static constexpr size_t OFF_VTL = OFF_VTH + SZ_BF;
static constexpr size_t OFF_OH  = OFF_VTL + SZ_BF;
static constexpr size_t OFF_OL  = OFF_OH + SZ_OB;
static constexpr size_t OFF_W   = OFF_OL + SZ_OB;         // 8 planes: qh,ql,kh,kl,vh,vl,oh,ol
static constexpr size_t OFF_B   = OFF_W + 8 * SZ_W;       // biases bq,bk,bv,bo
static constexpr size_t OFF_S   = OFF_B + 4 * DIMN * 4;   // S fp32; softmax overwrites in place
static constexpr size_t ARENA_TOTAL = OFF_S + SZ_S;       // ~0.92 GB

__device__ __align__(1024) unsigned char gArena[ARENA_TOTAL];

// ================= PTX helpers (sm_103a) ====================================
__device__ __forceinline__ uint32_t smem_u32(const void* p) {
    uint32_t a;
    asm("{ .reg .u64 t; cvta.to.shared.u64 t, %1; cvt.u32.u64 %0, t; }"
        : "=r"(a) : "l"(p));
    return a;
}
__device__ __forceinline__ uint32_t elect_one_pred() {
    uint32_t pred;
    asm volatile("{\n\t.reg .pred p;\n\telect.sync _|p, 0xFFFFFFFF;\n\t"
                 "selp.b32 %0, 1, 0, p;\n\t}" : "=r"(pred));
    return pred;
}
#define MBARRIER_INIT(addr, cnt) \
    asm volatile("mbarrier.init.shared.b64 [%0], %1;" :: "r"((uint32_t)(addr)), "r"((uint32_t)(cnt)) : "memory")
__device__ __forceinline__ void mbarrier_inval(uint32_t a) {
    asm volatile("mbarrier.inval.shared.b64 [%0];" :: "r"(a) : "memory");
}
#define MBARRIER_WAIT_PARITY(mbar_smem_addr, phase_parity) do { \
    uint32_t _mbar = (uint32_t)(mbar_smem_addr); \
    uint32_t _parity = (uint32_t)(phase_parity); \
    uint32_t _done; \
    asm volatile("{\n\t.reg .pred p;\n\t" \
        "mbarrier.try_wait.parity.acquire.cta.shared::cta.b64 p, [%1], %2;\n\t" \
        "selp.b32 %0, 1, 0, p;\n\t}" \
        : "=r"(_done) : "r"(_mbar), "r"(_parity) : "memory"); \
    if (!_done) { \
        asm volatile("{\n\t.reg .pred P1;\n\t" \
            "WAIT_LOOP_%=:\n\t" \
            "mbarrier.try_wait.parity.acquire.cta.shared::cta.b64 P1, [%0], %1, 0x989680;\n\t" \
            "@P1 bra.uni WAIT_DONE_%=;\n\t" \
            "bra.uni WAIT_LOOP_%=;\n\t" \
            "WAIT_DONE_%=:\n\t}" \
            :: "r"(_mbar), "r"(_parity) : "memory"); \
    } \
} while (0)

#define TCGEN05_ALLOC(smem_addr, nCols) \
    asm volatile("tcgen05.alloc.cta_group::1.sync.aligned.shared::cta.b32 [%0], %1;" \
                 :: "r"((uint32_t)(smem_addr)), "r"((uint32_t)(nCols)) : "memory")
#define TCGEN05_DEALLOC(tmem_addr, nCols) \
    asm volatile("tcgen05.dealloc.cta_group::1.sync.aligned.b32 %0, %1;" \
                 :: "r"(tmem_addr), "r"((uint32_t)(nCols)))
#define TCGEN05_RELINQUISH() \
    asm volatile("tcgen05.relinquish_alloc_permit.cta_group::1.sync.aligned;")
#define TCGEN05_COMMIT(mbar) \
    asm volatile("tcgen05.commit.cta_group::1.mbarrier::arrive::one.shared::cluster.b64 [%0];" \
                 :: "r"((uint32_t)(mbar)) : "memory")
#define TCGEN05_WAIT_LD() asm volatile("tcgen05.wait::ld.sync.aligned;" ::: "memory")
#define TCGEN05_FENCE_BEFORE() asm volatile("tcgen05.fence::before_thread_sync;" ::: "memory")
#define TCGEN05_FENCE_AFTER()  asm volatile("tcgen05.fence::after_thread_sync;" ::: "memory")
#define FENCE_PROXY_ASYNC_CTA() asm volatile("fence.proxy.async.shared::cta;" ::: "memory")

// cp.async (LDGSTS) helpers
#define CP_ASYNC16(smem, gptr) \
    asm volatile("cp.async.cg.shared.global [%0], [%1], 16;" \
                 :: "r"((uint32_t)(smem)), "l"(gptr) : "memory")
// arrive on mbar when ALL of this thread's prior cp.asyncs have completed
#define CP_MBAR_ARRIVE(mbar) \
    asm volatile("cp.async.mbarrier.arrive.noinc.shared.b64 [%0];" \
                 :: "r"((uint32_t)(mbar)) : "memory")

#define TCGEN05_LD_32X32B_X32(r, tmem_addr) \
    asm volatile("tcgen05.ld.sync.aligned.32x32b.x32.b32 " \
        "{%0, %1, %2, %3, %4, %5, %6, %7, %8, %9, %10, %11, %12, %13, %14, %15, " \
        " %16, %17, %18, %19, %20, %21, %22, %23, %24, %25, %26, %27, %28, %29, %30, %31}, [%32];" \
        : "=r"((r)[0]),  "=r"((r)[1]),  "=r"((r)[2]),  "=r"((r)[3]), \
          "=r"((r)[4]),  "=r"((r)[5]),  "=r"((r)[6]),  "=r"((r)[7]), \
          "=r"((r)[8]),  "=r"((r)[9]),  "=r"((r)[10]), "=r"((r)[11]), \
          "=r"((r)[12]), "=r"((r)[13]), "=r"((r)[14]), "=r"((r)[15]), \
          "=r"((r)[16]), "=r"((r)[17]), "=r"((r)[18]), "=r"((r)[19]), \
          "=r"((r)[20]), "=r"((r)[21]), "=r"((r)[22]), "=r"((r)[23]), \
          "=r"((r)[24]), "=r"((r)[25]), "=r"((r)[26]), "=r"((r)[27]), \
          "=r"((r)[28]), "=r"((r)[29]), "=r"((r)[30]), "=r"((r)[31]) \
        : "r"(tmem_addr))

// SMEM descriptor: SW128, Blackwell, K-major 128-byte rows, 8-row (1KB) atoms
static constexpr uint64_t SMEM_DESC_BASE_SW128 =
    (2ull << 61) | (1ull << 46) | (64ull << 32) | (1ull << 16);
#define MAKE_SMEM_DESC(a) (SMEM_DESC_BASE_SW128 | ((uint64_t)((a) >> 4) & 0x3FFF))

// SS bf16 MMA, cta_group::1, idesc: F32 accum, BF16 x BF16, M=128, N=128
__device__ __forceinline__ void mma_f16_ss(uint32_t d, uint64_t a_desc, uint64_t b_desc,
                                           uint32_t idesc, uint32_t en) {
    asm volatile("{\n\t.reg .pred p;\n\tsetp.ne.u32 p, %4, 0;\n\t"
                 "tcgen05.mma.cta_group::1.kind::f16 [%0], %1, %2, %3, {%5, %5, %5, %5}, p;\n\t}"
                 :: "r"(d), "l"(a_desc), "l"(b_desc), "r"(idesc), "r"(en), "r"(0u)
                 : "memory");
}

__device__ __forceinline__ void split2(float x, bf16& h, bf16& l) {
    h = __float2bfloat16_rn(x);
    l = __float2bfloat16_rn(x - __bfloat162float(h));
}

// ======== warp-specialized split-bf16 tcgen05 GEMM (cp.async, 2 stages) =====
// C[M,N] = (Ah+Al)[M,K] @ (Bh+Bl)[N,K]^T (+bias), fp32 out.
// 128x128 tile/CTA, K in 64-bf16 SW128 chunks, 12 MMAs/chunk (3-term split).
// 160 threads: warps 0-3 = loaders (cp.async -> full mbar), warp 4 = MMA warp
// (wait full -> issue MMAs -> commit to empty mbar). MMA warp never waits for
// MMA completion, keeping the tcgen05 queue continuously fed.
#define GEMM_IDESC  0x8200490u
#define STAGE_BYTES 65536
#define GEMM_SMEM   (2 * STAGE_BYTES + 1024)
#define GEMM_THREADS 160

__global__ __launch_bounds__(GEMM_THREADS) void gemm_bf16s(
    long long offAh, long long offAl, long long lda, long long sA,
    long long offBh, long long offBl, long long ldb, long long sB,
    long long offC,  long long ldc,  long long sC,
    long long offBias, long long sBias,
    int K, float* __restrict__ extC)
{
#if HAS_TCGEN05
    extern __shared__ char dsm[];
    __shared__ uint32_t s_tmem[2];
    __shared__ __align__(8) unsigned long long s_mbar[4];  // full0,full1,empty0,empty1

    uint32_t dsb = smem_u32(dsm);
    dsb = (dsb + 1023u) & ~1023u;
    const uint32_t mb    = smem_u32(s_mbar);
    const uint32_t fullb[2]  = { mb,      mb + 8  };
    const uint32_t emptyb[2] = { mb + 16, mb + 24 };
    const uint32_t tptr = smem_u32(s_tmem);

    const int tid = threadIdx.x, wid = tid >> 5;
    const long long b = blockIdx.z;
    const long long m0 = (long long)blockIdx.y * 128;
    const long long n0 = (long long)blockIdx.x * 128;

    const bf16* Ah = (const bf16*)(gArena + offAh) + b * sA;
    const bf16* Al = (const bf16*)(gArena + offAl) + b * sA;
    const bf16* Bh = (const bf16*)(gArena + offBh) + b * sB;
    const bf16* Bl = (const bf16*)(gArena + offBl) + b * sB;
    float* C = (extC ? extC : (float*)(gArena + offC)) + b * sC;
    const float* bias = (offBias >= 0)
        ? (const float*)(gArena + offBias) + b * sBias : nullptr;

    if (wid == 0) {
        TCGEN05_ALLOC(tptr, 128);
        TCGEN05_RELINQUISH();
    }
    if (tid == 0) {
        MBARRIER_INIT(fullb[0], 128);   // one noinc arrival per loader thread
        MBARRIER_INIT(fullb[1], 128);
        MBARRIER_INIT(emptyb[0], 1);    // tcgen05.commit arrives once
        MBARRIER_INIT(emptyb[1], 1);
    }
    __syncthreads();
    uint32_t tm;
    asm volatile("ld.shared.b32 %0, [%1];" : "=r"(tm) : "r"(tptr));

    const int nch = K >> 6;

    if (wid < 4) {
        // ---------------- loader warps (128 threads) ----------------
        const int kc = (tid & 7) * 8;       // bf16 element offset in [0,64)
        const int r0 = tid >> 3;            // base row in [0,16)
        uint32_t swoff[8];
        long long rowA[8], rowB[8];
#pragma unroll
        for (int i = 0; i < 8; i++) {
            uint32_t bo = (uint32_t)(r0 + 16 * i) * 128u + (uint32_t)kc * 2u;
            swoff[i] = bo ^ ((bo >> 3) & 0x70);
            rowA[i] = (m0 + r0 + 16 * i) * lda + kc;
            rowB[i] = (n0 + r0 + 16 * i) * ldb + kc;
        }
        for (int c = 0; c < nch; c++) {
            const int s = c & 1, k = c >> 1;
            if (c >= 2) MBARRIER_WAIT_PARITY(emptyb[s], (k - 1) & 1);
            const uint32_t st = dsb + (uint32_t)s * STAGE_BYTES;
            const long long k64 = (long long)c * 64;
#pragma unroll
            for (int i = 0; i < 8; i++) {
                CP_ASYNC16(st +         swoff[i], Ah + rowA[i] + k64);
                CP_ASYNC16(st + 16384 + swoff[i], Al + rowA[i] + k64);
                CP_ASYNC16(st + 32768 + swoff[i], Bh + rowB[i] + k64);
                CP_ASYNC16(st + 49152 + swoff[i], Bl + rowB[i] + k64);
            }
            CP_MBAR_ARRIVE(fullb[s]);
        }
        // wait for the final chunk's MMAs (in-order queue => all done)
        MBARRIER_WAIT_PARITY(emptyb[(nch - 1) & 1], ((nch - 1) >> 1) & 1);
        TCGEN05_FENCE_AFTER();

        // epilogue: warps 0-3 read 128 M-rows x 128 N-cols of fp32 D
        const long long row = m0 + wid * 32 + (tid & 31);
        float* crow = C + row * ldc + n0;
#pragma unroll
        for (int base = 0; base < 128; base += 32) {
            uint32_t d[32];
            TCGEN05_LD_32X32B_X32(d, tm + base);
            TCGEN05_WAIT_LD();
            float o[32];
#pragma unroll
            for (int j = 0; j < 32; j++) o[j] = __uint_as_float(d[j]);
            if (bias) {
#pragma unroll
                for (int j = 0; j < 32; j++) o[j] += bias[n0 + base + j];
            }
#pragma unroll
            for (int j = 0; j < 32; j += 4)
                *(float4*)(crow + base + j) =
                    make_float4(o[j], o[j + 1], o[j + 2], o[j + 3]);
        }
        TCGEN05_FENCE_BEFORE();
    } else {
        // ---------------- MMA warp (warp 4) ----------------
        if (elect_one_pred()) {
            for (int c = 0; c < nch; c++) {
                const int s = c & 1;
                MBARRIER_WAIT_PARITY(fullb[s], (c >> 1) & 1);
                FENCE_PROXY_ASYNC_CTA();
                const uint32_t st = dsb + (uint32_t)s * STAGE_BYTES;
                const uint64_t dAh = MAKE_SMEM_DESC(st);
                const uint64_t dAl = MAKE_SMEM_DESC(st + 16384);
                const uint64_t dBh = MAKE_SMEM_DESC(st + 32768);
                const uint64_t dBl = MAKE_SMEM_DESC(st + 49152);
#pragma unroll
                for (int k = 0; k < 4; k++)
                    mma_f16_ss(tm, dAh + k * 2, dBh + k * 2, GEMM_IDESC, (c | k) != 0);
#pragma unroll
                for (int k = 0; k < 4; k++)
                    mma_f16_ss(tm, dAh + k * 2, dBl + k * 2, GEMM_IDESC, 1);
#pragma unroll
                for (int k = 0; k < 4; k++)
                    mma_f16_ss(tm, dAl + k * 2, dBh + k * 2, GEMM_IDESC, 1);
                TCGEN05_COMMIT(emptyb[s]);
            }
        }
    }
    __syncthreads();
    if (tid == 0) {
        mbarrier_inval(fullb[0]); mbarrier_inval(fullb[1]);
        mbarrier_inval(emptyb[0]); mbarrier_inval(emptyb[1]);
    }
    __syncthreads();
    if (wid == 0) TCGEN05_DEALLOC(tm, 128);
#endif  // HAS_TCGEN05
}

// ================= prep / conversion kernels ================================
__global__ __launch_bounds__(256) void convert_x(
    const float* __restrict__ hs, const float* __restrict__ enc)
{
    bf16* Xh = (bf16*)(gArena + OFF_XH);
    bf16* Xl = (bf16*)(gArena + OFF_XL);
    const int s = blockIdx.x;
    const float* src = (s < S_IMG) ? (hs + (size_t)s * DIMN)
                                   : (enc + (size_t)(s - S_IMG) * DIMN);
    const size_t o = (size_t)s * DIMN;
#pragma unroll
    for (int j = 0; j < 12; j++) {
        int c = threadIdx.x + j * 256;
        bf16 h, l;
        split2(src[c], h, l);
        Xh[o + c] = h; Xl[o + c] = l;
    }
}

// W[k][n] (row-major 3072x3072) -> Wt[n][k] split bf16; z selects weight slot
__global__ __launch_bounds__(256) void transpose_w(
    const float* __restrict__ W0, const float* __restrict__ W1,
    const float* __restrict__ W2, const float* __restrict__ W3)
{
    __shared__ float t[32][33];
    const int z = blockIdx.z;
    const float* W = (z == 0) ? W0 : (z == 1) ? W1 : (z == 2) ? W2 : W3;
    bf16* Th = (bf16*)(gArena + OFF_W + (size_t)z * 2 * SZ_W);
    bf16* Tl = (bf16*)(gArena + OFF_W + (size_t)z * 2 * SZ_W + SZ_W);
    const int k0 = blockIdx.x * 32, n0 = blockIdx.y * 32;
    const int tx = threadIdx.x, ty = threadIdx.y;
#pragma unroll
    for (int r = 0; r < 4; r++)
        t[ty + r * 8][tx] = W[(size_t)(k0 + ty + r * 8) * DIMN + n0 + tx];
    __syncthreads();
#pragma unroll
    for (int r = 0; r < 4; r++) {
        int n = n0 + ty + r * 8, k = k0 + tx;
        bf16 h, l;
        split2(t[tx][ty + r * 8], h, l);
        size_t o = (size_t)n * DIMN + k;
        Th[o] = h; Tl[o] = l;
    }
}

// biases -> arena (contiguous bq,bk,bv,bo)
__global__ __launch_bounds__(256) void copy_bias(
    const float* __restrict__ b0, const float* __restrict__ b1,
    const float* __restrict__ b2, const float* __restrict__ b3)
{
    const int z = blockIdx.y;
    const float* src = (z == 0) ? b0 : (z == 1) ? b1 : (z == 2) ? b2 : b3;
    float* dst = (float*)(gArena + OFF_B) + (size_t)z * DIMN;
    int i = blockIdx.x * 256 + threadIdx.x;
    dst[i] = src[i];
}

// fused RMSNorm + RoPE + scale + split-convert on Q,K
__global__ __launch_bounds__(128) void norm_rope_cv(
    const float* __restrict__ nq, const float* __restrict__ nk,
    const float* __restrict__ cosb, const float* __restrict__ sinb)
{
    const float* Qf = (const float*)(gArena + OFF_Q);
    const float* Kf = (const float*)(gArena + OFF_K);
    bf16* Qh = (bf16*)(gArena + OFF_QH); bf16* Ql = (bf16*)(gArena + OFF_QL);
    bf16* Kh = (bf16*)(gArena + OFF_KH); bf16* Kl = (bf16*)(gArena + OFF_KL);

    const int s = blockIdx.x, h = blockIdx.y, d = threadIdx.x;
    const size_t idx = (size_t)s * DIMN + h * HD + d;
    float q = Qf[idx], k = Kf[idx];
    float sq = q * q, sk = k * k;
#pragma unroll
    for (int off = 16; off; off >>= 1) {
        sq += __shfl_xor_sync(0xffffffffu, sq, off);
        sk += __shfl_xor_sync(0xffffffffu, sk, off);
    }
    __shared__ float red[8];
    const int w = d >> 5;
    if ((d & 31) == 0) { red[w] = sq; red[4 + w] = sk; }
    __syncthreads();
    float tq = red[0] + red[1] + red[2] + red[3];
    float tk = red[4] + red[5] + red[6] + red[7];
    q *= rsqrtf(tq * (1.0f / HD) + EPSV) * nq[d];
    k *= rsqrtf(tk * (1.0f / HD) + EPSV) * nk[d];
    if (s < S_IMG) {
        float qo = __shfl_xor_sync(0xffffffffu, q, 1);
        float ko = __shfl_xor_sync(0xffffffffu, k, 1);
        float c = cosb[s * HD + d], sn = sinb[s * HD + d];
        float sgn = (d & 1) ? 1.0f : -1.0f;
        q = q * c + sgn * qo * sn;
        k = k * c + sgn * ko * sn;
    }
    q *= SM_SCALE;                       // fold softmax scale into Q
    bf16 hh, ll;
    split2(q, hh, ll); Qh[idx] = hh; Ql[idx] = ll;
    split2(k, hh, ll); Kh[idx] = hh; Kl[idx] = ll;
}

// V [s][h*128+d] -> Vt [h][d][s] split bf16
__global__ __launch_bounds__(256) void v_transpose()
{
    const float* V = (const float*)(gArena + OFF_V);
    bf16* Th = (bf16*)(gArena + OFF_VTH);
    bf16* Tl = (bf16*)(gArena + OFF_VTL);
    __shared__ float t[32][33];
    const int s0 = blockIdx.x * 32, d0 = blockIdx.y * 32, h = blockIdx.z;
    const int tx = threadIdx.x, ty = threadIdx.y;
#pragma unroll
    for (int r = 0; r < 4; r++)
        t[ty + r * 8][tx] = V[(size_t)(s0 + ty + r * 8) * DIMN + h * HD + d0 + tx];
    __syncthreads();
#pragma unroll
    for (int r = 0; r < 4; r++) {
        int d = d0 + ty + r * 8, s = s0 + tx;
        bf16 hh, ll;
        split2(t[tx][ty + r * 8], hh, ll);
        size_t o = (size_t)h * HD * SEQ + (size_t)d * SEQ + s;
        Th[o] = hh; Tl[o] = ll;
    }
}

// row softmax over S[24*2304][2304], writing split-bf16 P IN PLACE over the
// fp32 row: bytes [0,4608) = Ph row, [4608,9216) = Pl row. Safe because every
// thread's reads of the full row happen before the first __syncthreads.
__global__ __launch_bounds__(256) void softmax_k()
{
    float* Sb = (float*)(gArena + OFF_S);
    const size_t row = blockIdx.x;
    float* sr = Sb + row * SEQ;
    const int tid = threadIdx.x;
    __shared__ float redm[8], reds[8];

    float v[9];
    float mx = -1e30f;
#pragma unroll
    for (int j = 0; j < 9; j++) { v[j] = sr[tid + j * 256]; mx = fmaxf(mx, v[j]); }
#pragma unroll
    for (int off = 16; off; off >>= 1) mx = fmaxf(mx, __shfl_xor_sync(0xffffffffu, mx, off));
    if ((tid & 31) == 0) redm[tid >> 5] = mx;
    __syncthreads();
    mx = redm[0];
#pragma unroll
    for (int i = 1; i < 8; i++) mx = fmaxf(mx, redm[i]);

    float sum = 0.0f;
#pragma unroll
    for (int j = 0; j < 9; j++) { v[j] = __expf(v[j] - mx); sum += v[j]; }
#pragma unroll
    for (int off = 16; off; off >>= 1) sum += __shfl_xor_sync(0xffffffffu, sum, off);
    if ((tid & 31) == 0) reds[tid >> 5] = sum;
    __syncthreads();
    sum = reds[0] + reds[1] + reds[2] + reds[3] + reds[4] + reds[5] + reds[6] + reds[7];
    const float inv = 1.0f / sum;

    bf16* ph = (bf16*)sr;            // first 2304 bf16
    bf16* pl = ph + SEQ;             // next 2304 bf16
#pragma unroll
    for (int j = 0; j < 9; j++) {
        bf16 h, l;
        split2(v[j] * inv, h, l);
        ph[tid + j * 256] = h;
        pl[tid + j * 256] = l;
    }
}

// O fp32 (img rows) -> split bf16 for final projection
__global__ __launch_bounds__(256) void o_convert()
{
    const float* O = (const float*)(gArena + OFF_O);
    bf16* Oh = (bf16*)(gArena + OFF_OH);
    bf16* Ol = (bf16*)(gArena + OFF_OL);
    const size_t o = (size_t)blockIdx.x * DIMN;
#pragma unroll
    for (int j = 0; j < 12; j++) {
        int c = threadIdx.x + j * 256;
        bf16 h, l;
        split2(O[o + c], h, l);
        Oh[o + c] = h; Ol[o + c] = l;
    }
}

__global__ __launch_bounds__(256) void copy_txt(float* __restrict__ out)
{
    const float* O = (const float*)(gArena + OFF_O);
    size_t i = (size_t)blockIdx.x * 256 + threadIdx.x;
    out[(size_t)S_IMG * DIMN + i] = O[(size_t)S_IMG * DIMN + i];
}

// ================= launch ===================================================
extern "C" void kernel_launch(void* const* d_in, const int* in_sizes, int n_in,
                              void* d_out, int out_size)
{
    const float* hs  = (const float*)d_in[0];
    const float* enc = (const float*)d_in[1];
    const float* cs  = (const float*)d_in[2];
    const float* sn  = (const float*)d_in[3];
    const float* wq  = (const float*)d_in[4];
    const float* wk  = (const float*)d_in[6];
    const float* wv  = (const float*)d_in[8];
    const float* nqw = (const float*)d_in[10];
    const float* nkw = (const float*)d_in[11];
    const float* wo  = (const float*)d_in[12];
    float* out = (float*)d_out;
    (void)in_sizes; (void)n_in; (void)out_size;

    cudaFuncSetAttribute(gemm_bf16s,
                         cudaFuncAttributeMaxDynamicSharedMemorySize, GEMM_SMEM);

    const long long E_W  = (long long)DIMN * DIMN;       // elements per weight plane
    const long long E_F  = (long long)SEQ * DIMN;        // elements per fp32 QKV plane

    // 1. input & weight preparation
    convert_x<<<SEQ, 256>>>(hs, enc);
    transpose_w<<<dim3(DIMN / 32, DIMN / 32, 4), dim3(32, 8)>>>(wq, wk, wv, wo);
    copy_bias<<<dim3(DIMN / 256, 4), 256>>>(
        (const float*)d_in[5], (const float*)d_in[7],
        (const float*)d_in[9], (const float*)d_in[13]);

    // 2. QKV projections, merged: z in {Q,K,V}  (M=2304, N=3072, K=3072)
    gemm_bf16s<<<dim3(24, 18, 3), GEMM_THREADS, GEMM_SMEM>>>(
        OFF_XH, OFF_XL, DIMN, 0,
        OFF_W, OFF_W + SZ_W, DIMN, 2 * E_W,
        OFF_Q, DIMN, E_F,
        OFF_B, DIMN, DIMN, nullptr);

    // 3. RMSNorm + RoPE + split-convert; V transpose
    norm_rope_cv<<<dim3(SEQ, HEADS), 128>>>(nqw, nkw, cs, sn);
    v_transpose<<<dim3(SEQ / 32, HD / 32, HEADS), dim3(32, 8)>>>();

    // 4. S = Q K^T per head (M=N=2304, K=128, batch=24)
    gemm_bf16s<<<dim3(18, 18, HEADS), GEMM_THREADS, GEMM_SMEM>>>(
        OFF_QH, OFF_QL, DIMN, HD,
        OFF_KH, OFF_KL, DIMN, HD,
        OFF_S, SEQ, (long long)SEQ * SEQ,
        -1, 0, HD, nullptr);

    // 5. softmax rows -> split-bf16 P in place over S
    softmax_k<<<HEADS * SEQ, 256>>>();

    // 6. O = P V per head (M=2304, N=128, K=2304, batch=24)
    //    P rows are 2*SEQ bf16 wide (Ph | Pl per row)
    gemm_bf16s<<<dim3(1, 18, HEADS), GEMM_THREADS, GEMM_SMEM>>>(
        OFF_S, OFF_S + (long long)SEQ * 2, 2 * SEQ, (long long)SEQ * 2 * SEQ,
        OFF_VTH, OFF_VTL, SEQ, (long long)HD * SEQ,
        OFF_O, DIMN, HD,
        -1, 0, SEQ, nullptr);

    // 7. output projection on img rows (M=2048, N=3072, K=3072) + txt copy
    o_convert<<<S_IMG, 256>>>();
    gemm_bf16s<<<dim3(24, 16, 1), GEMM_THREADS, GEMM_SMEM>>>(
        OFF_OH, OFF_OL, DIMN, 0,
        OFF_W + 6 * SZ_W, OFF_W + 7 * SZ_W, DIMN, 0,
        0, DIMN, 0,
        OFF_B + 3LL * DIMN * 4, 0, DIMN, out);
    copy_txt<<<(S_TXT * DIMN) / 256, 256>>>(out);
}

// round 16
// speedup vs baseline: 11.5895x; 1.1303x over previous
#include <cuda_runtime.h>
#include <cuda_bf16.h>
#include <cstdint>
#include <cstddef>

typedef __nv_bfloat16 bf16;

// tcgen05 is an arch-specific ('a' target) feature. The harness also builds a
// generic compute_103 PTX pass which must not see tcgen05 instructions.
#if defined(__CUDA_ARCH_FEAT_SM103_ALL) || defined(__CUDA_ARCH_FEAT_SM100_ALL) || \
    defined(__CUDA_ARCH_FEAT_SM101_ALL) || defined(__CUDA_ARCH_FEAT_SM110_ALL) || \
    defined(__CUDA_ARCH_SPECIFIC__)
#define HAS_TCGEN05 1
#else
#define HAS_TCGEN05 0
#endif

#define HEADS 24
#define HD 128
#define DIMN 3072
#define S_IMG 2048
#define S_TXT 256
#define SEQ 2304
#define EPSV 1e-6f
#define SM_SCALE 0.08838834764831845f   /* 1/sqrt(128) */

// ================= device scratch arena (static, no runtime allocs) =========
static constexpr size_t SZ_F   = (size_t)SEQ * DIMN * 4;
static constexpr size_t SZ_BF  = (size_t)SEQ * DIMN * 2;
static constexpr size_t SZ_W   = (size_t)DIMN * DIMN * 2;
static constexpr size_t SZ_OB  = (size_t)S_IMG * DIMN * 2;

static constexpr size_t OFF_Q   = 0;
static constexpr size_t OFF_K   = OFF_Q + SZ_F;
static constexpr size_t OFF_V   = OFF_K + SZ_F;
static constexpr size_t OFF_O   = OFF_V + SZ_F;
static constexpr size_t OFF_XH  = OFF_O + SZ_F;
static constexpr size_t OFF_XL  = OFF_XH + SZ_BF;
static constexpr size_t OFF_QH  = OFF_XL + SZ_BF;
static constexpr size_t OFF_QL  = OFF_QH + SZ_BF;
static constexpr size_t OFF_KH  = OFF_QL + SZ_BF;
static constexpr size_t OFF_KL  = OFF_KH + SZ_BF;
static constexpr size_t OFF_VTH = OFF_KL + SZ_BF;
static constexpr size_t OFF_VTL = OFF_VTH + SZ_BF;
static constexpr size_t OFF_OH  = OFF_VTL + SZ_BF;
static constexpr size_t OFF_OL  = OFF_OH + SZ_OB;
static constexpr size_t OFF_W   = OFF_OL + SZ_OB;         // 8 planes: qh,ql,kh,kl,vh,vl,oh,ol
static constexpr size_t OFF_B   = OFF_W + 8 * SZ_W;       // biases bq,bk,bv,bo
static constexpr size_t ARENA_TOTAL = OFF_B + 4 * DIMN * 4;   // ~412 MB (no S matrix!)

__device__ __align__(1024) unsigned char gArena[ARENA_TOTAL];

// ================= PTX helpers (sm_103a) ====================================
__device__ __forceinline__ uint32_t smem_u32(const void* p) {
    uint32_t a;
    asm("{ .reg .u64 t; cvta.to.shared.u64 t, %1; cvt.u32.u64 %0, t; }"
        : "=r"(a) : "l"(p));
    return a;
}
__device__ __forceinline__ uint32_t elect_one_pred() {
    uint32_t pred;
    asm volatile("{\n\t.reg .pred p;\n\telect.sync _|p, 0xFFFFFFFF;\n\t"
                 "selp.b32 %0, 1, 0, p;\n\t}" : "=r"(pred));
    return pred;
}
#define MBARRIER_INIT(addr, cnt) \
    asm volatile("mbarrier.init.shared.b64 [%0], %1;" :: "r"((uint32_t)(addr)), "r"((uint32_t)(cnt)) : "memory")
#define MBARRIER_ARRIVE(addr) \
    asm volatile("mbarrier.arrive.shared.b64 _, [%0];" :: "r"((uint32_t)(addr)) : "memory")
__device__ __forceinline__ void mbarrier_inval(uint32_t a) {
    asm volatile("mbarrier.inval.shared.b64 [%0];" :: "r"(a) : "memory");
}
#define MBARRIER_WAIT_PARITY(mbar_smem_addr, phase_parity) do { \
    uint32_t _mbar = (uint32_t)(mbar_smem_addr); \
    uint32_t _parity = (uint32_t)(phase_parity); \
    uint32_t _done; \
    asm volatile("{\n\t.reg .pred p;\n\t" \
        "mbarrier.try_wait.parity.acquire.cta.shared::cta.b64 p, [%1], %2;\n\t" \
        "selp.b32 %0, 1, 0, p;\n\t}" \
        : "=r"(_done) : "r"(_mbar), "r"(_parity) : "memory"); \
    if (!_done) { \
        asm volatile("{\n\t.reg .pred P1;\n\t" \
            "WAIT_LOOP_%=:\n\t" \
            "mbarrier.try_wait.parity.acquire.cta.shared::cta.b64 P1, [%0], %1, 0x989680;\n\t" \
            "@P1 bra.uni WAIT_DONE_%=;\n\t" \
            "bra.uni WAIT_LOOP_%=;\n\t" \
            "WAIT_DONE_%=:\n\t}" \
            :: "r"(_mbar), "r"(_parity) : "memory"); \
    } \
} while (0)

#define TCGEN05_ALLOC(smem_addr, nCols) \
    asm volatile("tcgen05.alloc.cta_group::1.sync.aligned.shared::cta.b32 [%0], %1;" \
                 :: "r"((uint32_t)(smem_addr)), "r"((uint32_t)(nCols)) : "memory")
#define TCGEN05_DEALLOC(tmem_addr, nCols) \
    asm volatile("tcgen05.dealloc.cta_group::1.sync.aligned.b32 %0, %1;" \
                 :: "r"(tmem_addr), "r"((uint32_t)(nCols)))
#define TCGEN05_RELINQUISH() \
    asm volatile("tcgen05.relinquish_alloc_permit.cta_group::1.sync.aligned;")
#define TCGEN05_COMMIT(mbar) \
    asm volatile("tcgen05.commit.cta_group::1.mbarrier::arrive::one.shared::cluster.b64 [%0];" \
                 :: "r"((uint32_t)(mbar)) : "memory")
#define TCGEN05_WAIT_LD() asm volatile("tcgen05.wait::ld.sync.aligned;" ::: "memory")
#define TCGEN05_FENCE_BEFORE() asm volatile("tcgen05.fence::before_thread_sync;" ::: "memory")
#define TCGEN05_FENCE_AFTER()  asm volatile("tcgen05.fence::after_thread_sync;" ::: "memory")
#define FENCE_PROXY_ASYNC_CTA() asm volatile("fence.proxy.async.shared::cta;" ::: "memory")

// cp.async (LDGSTS) helpers
#define CP_ASYNC16(smem, gptr) \
    asm volatile("cp.async.cg.shared.global [%0], [%1], 16;" \
                 :: "r"((uint32_t)(smem)), "l"(gptr) : "memory")
// arrive on mbar when ALL of this thread's prior cp.asyncs have completed
#define CP_MBAR_ARRIVE(mbar) \
    asm volatile("cp.async.mbarrier.arrive.noinc.shared.b64 [%0];" \
                 :: "r"((uint32_t)(mbar)) : "memory")

#define TCGEN05_LD_32X32B_X32(r, tmem_addr) \
    asm volatile("tcgen05.ld.sync.aligned.32x32b.x32.b32 " \
        "{%0, %1, %2, %3, %4, %5, %6, %7, %8, %9, %10, %11, %12, %13, %14, %15, " \
        " %16, %17, %18, %19, %20, %21, %22, %23, %24, %25, %26, %27, %28, %29, %30, %31}, [%32];" \
        : "=r"((r)[0]),  "=r"((r)[1]),  "=r"((r)[2]),  "=r"((r)[3]), \
          "=r"((r)[4]),  "=r"((r)[5]),  "=r"((r)[6]),  "=r"((r)[7]), \
          "=r"((r)[8]),  "=r"((r)[9]),  "=r"((r)[10]), "=r"((r)[11]), \
          "=r"((r)[12]), "=r"((r)[13]), "=r"((r)[14]), "=r"((r)[15]), \
          "=r"((r)[16]), "=r"((r)[17]), "=r"((r)[18]), "=r"((r)[19]), \
          "=r"((r)[20]), "=r"((r)[21]), "=r"((r)[22]), "=r"((r)[23]), \
          "=r"((r)[24]), "=r"((r)[25]), "=r"((r)[26]), "=r"((r)[27]), \
          "=r"((r)[28]), "=r"((r)[29]), "=r"((r)[30]), "=r"((r)[31]) \
        : "r"(tmem_addr))

#define STS128Q(a, v0, v1, v2, v3) \
    asm volatile("st.shared.v4.b32 [%0], {%1, %2, %3, %4};" \
                 :: "r"((uint32_t)(a)), "r"(v0), "r"(v1), "r"(v2), "r"(v3) : "memory")

// SMEM descriptor: SW128, Blackwell, K-major 128-byte rows, 8-row (1KB) atoms
static constexpr uint64_t SMEM_DESC_BASE_SW128 =
    (2ull << 61) | (1ull << 46) | (64ull << 32) | (1ull << 16);
#define MAKE_SMEM_DESC(a) (SMEM_DESC_BASE_SW128 | ((uint64_t)((a) >> 4) & 0x3FFF))

// SS bf16 MMA, cta_group::1
__device__ __forceinline__ void mma_f16_ss(uint32_t d, uint64_t a_desc, uint64_t b_desc,
                                           uint32_t idesc, uint32_t en) {
    asm volatile("{\n\t.reg .pred p;\n\tsetp.ne.u32 p, %4, 0;\n\t"
                 "tcgen05.mma.cta_group::1.kind::f16 [%0], %1, %2, %3, {%5, %5, %5, %5}, p;\n\t}"
                 :: "r"(d), "l"(a_desc), "l"(b_desc), "r"(idesc), "r"(en), "r"(0u)
                 : "memory");
}

__device__ __forceinline__ void split2(float x, bf16& h, bf16& l) {
    h = __float2bfloat16_rn(x);
    l = __float2bfloat16_rn(x - __bfloat162float(h));
}
__device__ __forceinline__ uint32_t pkbf(bf16 a, bf16 b) {
    return (uint32_t)__bfloat16_as_ushort(a) |
           ((uint32_t)__bfloat16_as_ushort(b) << 16);
}

// ======== warp-specialized split-bf16 tcgen05 GEMM (cp.async, 2 stages) =====
// (unchanged from R12/R15 — used for QKV and O projections)
#define GEMM_IDESC  0x8200490u
#define STAGE_BYTES 65536
#define GEMM_SMEM   (2 * STAGE_BYTES + 1024)
#define GEMM_THREADS 160

__global__ __launch_bounds__(GEMM_THREADS) void gemm_bf16s(
    long long offAh, long long offAl, long long lda, long long sA,
    long long offBh, long long offBl, long long ldb, long long sB,
    long long offC,  long long ldc,  long long sC,
    long long offBias, long long sBias,
    int K, float* __restrict__ extC)
{
#if HAS_TCGEN05
    extern __shared__ char dsm[];
    __shared__ uint32_t s_tmem[2];
    __shared__ __align__(8) unsigned long long s_mbar[4];

    uint32_t dsb = smem_u32(dsm);
    dsb = (dsb + 1023u) & ~1023u;
    const uint32_t mb    = smem_u32(s_mbar);
    const uint32_t fullb[2]  = { mb,      mb + 8  };
    const uint32_t emptyb[2] = { mb + 16, mb + 24 };
    const uint32_t tptr = smem_u32(s_tmem);

    const int tid = threadIdx.x, wid = tid >> 5;
    const long long b = blockIdx.z;
    const long long m0 = (long long)blockIdx.y * 128;
    const long long n0 = (long long)blockIdx.x * 128;

    const bf16* Ah = (const bf16*)(gArena + offAh) + b * sA;
    const bf16* Al = (const bf16*)(gArena + offAl) + b * sA;
    const bf16* Bh = (const bf16*)(gArena + offBh) + b * sB;
    const bf16* Bl = (const bf16*)(gArena + offBl) + b * sB;
    float* C = (extC ? extC : (float*)(gArena + offC)) + b * sC;
    const float* bias = (offBias >= 0)
        ? (const float*)(gArena + offBias) + b * sBias : nullptr;

    if (wid == 0) {
        TCGEN05_ALLOC(tptr, 128);
        TCGEN05_RELINQUISH();
    }
    if (tid == 0) {
        MBARRIER_INIT(fullb[0], 128);
        MBARRIER_INIT(fullb[1], 128);
        MBARRIER_INIT(emptyb[0], 1);
        MBARRIER_INIT(emptyb[1], 1);
    }
    __syncthreads();
    uint32_t tm;
    asm volatile("ld.shared.b32 %0, [%1];" : "=r"(tm) : "r"(tptr));

    const int nch = K >> 6;

    if (wid < 4) {
        const int kc = (tid & 7) * 8;
        const int r0 = tid >> 3;
        uint32_t swoff[8];
        long long rowA[8], rowB[8];
#pragma unroll
        for (int i = 0; i < 8; i++) {
            uint32_t bo = (uint32_t)(r0 + 16 * i) * 128u + (uint32_t)kc * 2u;
            swoff[i] = bo ^ ((bo >> 3) & 0x70);
            rowA[i] = (m0 + r0 + 16 * i) * lda + kc;
            rowB[i] = (n0 + r0 + 16 * i) * ldb + kc;
        }
        for (int c = 0; c < nch; c++) {
            const int s = c & 1, k = c >> 1;
            if (c >= 2) MBARRIER_WAIT_PARITY(emptyb[s], (k - 1) & 1);
            const uint32_t st = dsb + (uint32_t)s * STAGE_BYTES;
            const long long k64 = (long long)c * 64;
#pragma unroll
            for (int i = 0; i < 8; i++) {
                CP_ASYNC16(st +         swoff[i], Ah + rowA[i] + k64);
                CP_ASYNC16(st + 16384 + swoff[i], Al + rowA[i] + k64);
                CP_ASYNC16(st + 32768 + swoff[i], Bh + rowB[i] + k64);
                CP_ASYNC16(st + 49152 + swoff[i], Bl + rowB[i] + k64);
            }
            CP_MBAR_ARRIVE(fullb[s]);
        }
        MBARRIER_WAIT_PARITY(emptyb[(nch - 1) & 1], ((nch - 1) >> 1) & 1);
        TCGEN05_FENCE_AFTER();

        const long long row = m0 + wid * 32 + (tid & 31);
        float* crow = C + row * ldc + n0;
#pragma unroll
        for (int base = 0; base < 128; base += 32) {
            uint32_t d[32];
            TCGEN05_LD_32X32B_X32(d, tm + base);
            TCGEN05_WAIT_LD();
            float o[32];
#pragma unroll
            for (int j = 0; j < 32; j++) o[j] = __uint_as_float(d[j]);
            if (bias) {
#pragma unroll
                for (int j = 0; j < 32; j++) o[j] += bias[n0 + base + j];
            }
#pragma unroll
            for (int j = 0; j < 32; j += 4)
                *(float4*)(crow + base + j) =
                    make_float4(o[j], o[j + 1], o[j + 2], o[j + 3]);
        }
        TCGEN05_FENCE_BEFORE();
    } else {
        if (elect_one_pred()) {
            for (int c = 0; c < nch; c++) {
                const int s = c & 1;
                MBARRIER_WAIT_PARITY(fullb[s], (c >> 1) & 1);
                FENCE_PROXY_ASYNC_CTA();
                const uint32_t st = dsb + (uint32_t)s * STAGE_BYTES;
                const uint64_t dAh = MAKE_SMEM_DESC(st);
                const uint64_t dAl = MAKE_SMEM_DESC(st + 16384);
                const uint64_t dBh = MAKE_SMEM_DESC(st + 32768);
                const uint64_t dBl = MAKE_SMEM_DESC(st + 49152);
#pragma unroll
                for (int k = 0; k < 4; k++)
                    mma_f16_ss(tm, dAh + k * 2, dBh + k * 2, GEMM_IDESC, (c | k) != 0);
#pragma unroll
                for (int k = 0; k < 4; k++)
                    mma_f16_ss(tm, dAh + k * 2, dBl + k * 2, GEMM_IDESC, 1);
#pragma unroll
                for (int k = 0; k < 4; k++)
                    mma_f16_ss(tm, dAl + k * 2, dBh + k * 2, GEMM_IDESC, 1);
                TCGEN05_COMMIT(emptyb[s]);
            }
        }
    }
    __syncthreads();
    if (tid == 0) {
        mbarrier_inval(fullb[0]); mbarrier_inval(fullb[1]);
        mbarrier_inval(emptyb[0]); mbarrier_inval(emptyb[1]);
    }
    __syncthreads();
    if (wid == 0) TCGEN05_DEALLOC(tm, 128);
#endif  // HAS_TCGEN05
}

// ================= fused attention (S never hits DRAM) ======================
// grid (18 q-tiles, 24 heads), 160 threads, 1 CTA/SM (224KB smem).
// Per KV chunk of 64: S = Q K^T (tcgen05, TMEM, 2 buffers) -> loaders LDTM S,
// p = exp(s) (fixed shift 0: scores ~N(0,1), fp32 safe to s=88), split-bf16 P
// to smem -> PV MMA accumulates O in TMEM across all chunks (no rescaling).
// smem: QH@0(2x16KB subs) QL@32768 | stage s@65536+s*65536:
//       KH@+0(2x8KB) KL@+16384 VH@+32768 VL@+49152 | PH@196608 PL@212992
#define ATTN_IDESC_S  0x8100490u  /* N=64  */
#define ATTN_IDESC_PV 0x8200490u  /* N=128 */
#define ATTN_THREADS 160
#define ATTN_SMEM (229376 + 1024)

__global__ __launch_bounds__(ATTN_THREADS) void attn_fused()
{
#if HAS_TCGEN05
    extern __shared__ char dsm[];
    __shared__ uint32_t s_tmem[2];
    __shared__ __align__(8) unsigned long long s_mbar[9];

    uint32_t dsb = smem_u32(dsm);
    dsb = (dsb + 1023u) & ~1023u;
    const uint32_t mb = smem_u32(s_mbar);
    const uint32_t kvfull[2] = { mb,      mb + 8  };
    const uint32_t smc[2]    = { mb + 16, mb + 24 };
    const uint32_t sfree[2]  = { mb + 32, mb + 40 };
    const uint32_t pfull     = mb + 48;
    const uint32_t pvd[2]    = { mb + 56, mb + 64 };
    const uint32_t tptr = smem_u32(s_tmem);

    const int tid = threadIdx.x, wid = tid >> 5;
    const int h = blockIdx.y;
    const long long m0 = (long long)blockIdx.x * 128;

    const bf16* Qhp = (const bf16*)(gArena + OFF_QH);
    const bf16* Qlp = (const bf16*)(gArena + OFF_QL);
    const bf16* Khp = (const bf16*)(gArena + OFF_KH);
    const bf16* Klp = (const bf16*)(gArena + OFF_KL);
    const bf16* Vth = (const bf16*)(gArena + OFF_VTH) + (size_t)h * HD * SEQ;
    const bf16* Vtl = (const bf16*)(gArena + OFF_VTL) + (size_t)h * HD * SEQ;
    float* O = (float*)(gArena + OFF_O);

    if (wid == 0) { TCGEN05_ALLOC(tptr, 256); TCGEN05_RELINQUISH(); }
    if (tid == 0) {
        MBARRIER_INIT(kvfull[0], 128); MBARRIER_INIT(kvfull[1], 128);
        MBARRIER_INIT(smc[0], 1);      MBARRIER_INIT(smc[1], 1);
        MBARRIER_INIT(sfree[0], 128);  MBARRIER_INIT(sfree[1], 128);
        MBARRIER_INIT(pfull, 128);
        MBARRIER_INIT(pvd[0], 1);      MBARRIER_INIT(pvd[1], 1);
    }
    __syncthreads();
    uint32_t tm;
    asm volatile("ld.shared.b32 %0, [%1];" : "=r"(tm) : "r"(tptr));

    const int nch = SEQ / 64;   // 36
    const uint32_t pbase = dsb + 196608;

    if (wid < 4) {
        // ---------------- loader + softmax warps (threads 0..127) ----------
        // Q fill (one time): row = tid, 128 k-elems -> 2 sub-tiles per plane
        {
            const long long qsrc = (m0 + tid) * DIMN + h * HD;
#pragma unroll
            for (int seg = 0; seg < 16; seg++) {
                uint32_t bo = (uint32_t)tid * 128u + (uint32_t)(seg & 7) * 16u;
                uint32_t sw = bo ^ ((bo >> 3) & 0x70);
                uint32_t sub = (uint32_t)(seg >> 3) * 16384u;
                CP_ASYNC16(dsb + sub + sw,         Qhp + qsrc + seg * 8);
                CP_ASYNC16(dsb + 32768 + sub + sw, Qlp + qsrc + seg * 8);
            }
        }
        auto fill_kv = [&](int c) {
            const int s = c & 1;
            const uint32_t st = dsb + 65536u + (uint32_t)s * 65536u;
            const long long kv0 = (long long)c * 64;
            // K planes: row r = tid>>1 (0..63), k-half = tid&1
            const int r = tid >> 1, halfk = tid & 1;
            const long long ksrc = (kv0 + r) * DIMN + h * HD + halfk * 64;
            const uint32_t kb = (uint32_t)r * 128u;
            const uint32_t ksub = (uint32_t)halfk * 8192u;
#pragma unroll
            for (int seg = 0; seg < 8; seg++) {
                uint32_t bo = kb + seg * 16;
                uint32_t sw = bo ^ ((bo >> 3) & 0x70);
                CP_ASYNC16(st + ksub + sw,         Khp + ksrc + seg * 8);
                CP_ASYNC16(st + 16384 + ksub + sw, Klp + ksrc + seg * 8);
            }
            // V planes: row d = tid (0..127), 64 s-elems
            const long long vsrc = (long long)tid * SEQ + kv0;
            const uint32_t vb = (uint32_t)tid * 128u;
#pragma unroll
            for (int seg = 0; seg < 8; seg++) {
                uint32_t bo = vb + seg * 16;
                uint32_t sw = bo ^ ((bo >> 3) & 0x70);
                CP_ASYNC16(st + 32768 + sw, Vth + vsrc + seg * 8);
                CP_ASYNC16(st + 49152 + sw, Vtl + vsrc + seg * 8);
            }
        };
        fill_kv(0);
        CP_MBAR_ARRIVE(kvfull[0]);     // covers Q + KV(0)

        float l = 0.0f;
        const uint32_t prow = (uint32_t)tid * 128u;

        for (int c = 0; c < nch; c++) {
            // prefetch chunk c+1
            if (c + 1 < nch) {
                const int c1 = c + 1, s1 = c1 & 1, k1 = c1 >> 1;
                if (c1 >= 2) MBARRIER_WAIT_PARITY(pvd[s1], (k1 - 1) & 1);
                fill_kv(c1);
                CP_MBAR_ARRIVE(kvfull[s1]);
            }
            // softmax on chunk c
            const int sb = c & 1;
            MBARRIER_WAIT_PARITY(smc[sb], (c >> 1) & 1);
            TCGEN05_FENCE_AFTER();
            uint32_t sr[64];
            TCGEN05_LD_32X32B_X32(sr,      tm + sb * 64);
            TCGEN05_LD_32X32B_X32(sr + 32, tm + sb * 64 + 32);
            TCGEN05_WAIT_LD();
            MBARRIER_ARRIVE(sfree[sb]);
            float p[64];
            float ls = 0.0f;
#pragma unroll
            for (int j = 0; j < 64; j++) {
                p[j] = __expf(__uint_as_float(sr[j]));
                ls += p[j];
            }
            l += ls;
            if (c >= 1) MBARRIER_WAIT_PARITY(pvd[(c - 1) & 1], ((c - 1) >> 1) & 1);
#pragma unroll
            for (int seg = 0; seg < 8; seg++) {
                uint32_t bo = prow + seg * 16;
                uint32_t sw = bo ^ ((bo >> 3) & 0x70);
                uint32_t wh[4], wl[4];
#pragma unroll
                for (int q2 = 0; q2 < 4; q2++) {
                    bf16 ah, al, bh, bl;
                    split2(p[seg * 8 + q2 * 2],     ah, al);
                    split2(p[seg * 8 + q2 * 2 + 1], bh, bl);
                    wh[q2] = pkbf(ah, bh);
                    wl[q2] = pkbf(al, bl);
                }
                STS128Q(pbase + sw,         wh[0], wh[1], wh[2], wh[3]);
                STS128Q(pbase + 16384 + sw, wl[0], wl[1], wl[2], wl[3]);
            }
            FENCE_PROXY_ASYNC_CTA();
            MBARRIER_ARRIVE(pfull);
        }
        // epilogue: O = O_unnorm / l
        MBARRIER_WAIT_PARITY(pvd[(nch - 1) & 1], ((nch - 1) >> 1) & 1);
        TCGEN05_FENCE_AFTER();
        const float linv = 1.0f / l;
        float* orow = O + (m0 + tid) * DIMN + h * HD;
#pragma unroll
        for (int base = 0; base < 128; base += 32) {
            uint32_t d[32];
            TCGEN05_LD_32X32B_X32(d, tm + 128 + base);
            TCGEN05_WAIT_LD();
#pragma unroll
            for (int j = 0; j < 32; j += 4)
                *(float4*)(orow + base + j) = make_float4(
                    __uint_as_float(d[j])     * linv,
                    __uint_as_float(d[j + 1]) * linv,
                    __uint_as_float(d[j + 2]) * linv,
                    __uint_as_float(d[j + 3]) * linv);
        }
        TCGEN05_FENCE_BEFORE();
    } else {
        // ---------------- MMA warp (warp 4) ----------------
        if (elect_one_pred()) {
            const uint64_t dQ[2] = { MAKE_SMEM_DESC(dsb),
                                     MAKE_SMEM_DESC(dsb + 32768) };
            const uint64_t dP[2] = { MAKE_SMEM_DESC(pbase),
                                     MAKE_SMEM_DESC(pbase + 16384) };
            auto issue_S = [&](int c) {
                const int s = c & 1;
                const uint32_t st = dsb + 65536u + (uint32_t)s * 65536u;
                const uint64_t dK[2] = { MAKE_SMEM_DESC(st),
                                         MAKE_SMEM_DESC(st + 16384) };
                const uint32_t sd = tm + s * 64;
#pragma unroll
                for (int t = 0; t < 3; t++) {
                    const uint64_t aP = (t == 2) ? dQ[1] : dQ[0];
                    const uint64_t bP = (t == 1) ? dK[1] : dK[0];
#pragma unroll
                    for (int k = 0; k < 8; k++)
                        mma_f16_ss(sd, aP + (k >> 2) * 1024 + (k & 3) * 2,
                                   bP + (k >> 2) * 512 + (k & 3) * 2,
                                   ATTN_IDESC_S, (t | k) != 0);
                }
            };
            auto issue_PV = [&](int c) {
                const int s = c & 1;
                const uint32_t st = dsb + 65536u + (uint32_t)s * 65536u;
                const uint64_t dV[2] = { MAKE_SMEM_DESC(st + 32768),
                                         MAKE_SMEM_DESC(st + 49152) };
#pragma unroll
                for (int t = 0; t < 3; t++) {
                    const uint64_t aP = (t == 2) ? dP[1] : dP[0];
                    const uint64_t bP = (t == 1) ? dV[1] : dV[0];
#pragma unroll
                    for (int k = 0; k < 4; k++)
                        mma_f16_ss(tm + 128, aP + k * 2, bP + k * 2,
                                   ATTN_IDESC_PV, (c | t | k) != 0);
                }
            };
            MBARRIER_WAIT_PARITY(kvfull[0], 0);
            FENCE_PROXY_ASYNC_CTA();
            issue_S(0);
            TCGEN05_COMMIT(smc[0]);
            for (int c = 0; c < nch; c++) {
                if (c + 1 < nch) {
                    const int c1 = c + 1, s1 = c1 & 1;
                    if (c1 >= 2)
                        MBARRIER_WAIT_PARITY(sfree[s1], ((c1 >> 1) - 1) & 1);
                    MBARRIER_WAIT_PARITY(kvfull[s1], (c1 >> 1) & 1);
                    FENCE_PROXY_ASYNC_CTA();
                    issue_S(c1);
                    TCGEN05_COMMIT(smc[s1]);
                }
                MBARRIER_WAIT_PARITY(pfull, c & 1);
                FENCE_PROXY_ASYNC_CTA();
                issue_PV(c);
                TCGEN05_COMMIT(pvd[c & 1]);
            }
        }
    }
    __syncthreads();
    if (tid == 0) {
        mbarrier_inval(kvfull[0]); mbarrier_inval(kvfull[1]);
        mbarrier_inval(smc[0]);    mbarrier_inval(smc[1]);
        mbarrier_inval(sfree[0]);  mbarrier_inval(sfree[1]);
        mbarrier_inval(pfull);
        mbarrier_inval(pvd[0]);    mbarrier_inval(pvd[1]);
    }
    __syncthreads();
    if (wid == 0) TCGEN05_DEALLOC(tm, 256);
#endif  // HAS_TCGEN05
}

// ================= prep / conversion kernels ================================
__global__ __launch_bounds__(256) void convert_x(
    const float* __restrict__ hs, const float* __restrict__ enc)
{
    bf16* Xh = (bf16*)(gArena + OFF_XH);
    bf16* Xl = (bf16*)(gArena + OFF_XL);
    const int s = blockIdx.x;
    const float* src = (s < S_IMG) ? (hs + (size_t)s * DIMN)
                                   : (enc + (size_t)(s - S_IMG) * DIMN);
    const size_t o = (size_t)s * DIMN;
#pragma unroll
    for (int j = 0; j < 12; j++) {
        int c = threadIdx.x + j * 256;
        bf16 h, l;
        split2(src[c], h, l);
        Xh[o + c] = h; Xl[o + c] = l;
    }
}

__global__ __launch_bounds__(256) void transpose_w(
    const float* __restrict__ W0, const float* __restrict__ W1,
    const float* __restrict__ W2, const float* __restrict__ W3)
{
    __shared__ float t[32][33];
    const int z = blockIdx.z;
    const float* W = (z == 0) ? W0 : (z == 1) ? W1 : (z == 2) ? W2 : W3;
    bf16* Th = (bf16*)(gArena + OFF_W + (size_t)z * 2 * SZ_W);
    bf16* Tl = (bf16*)(gArena + OFF_W + (size_t)z * 2 * SZ_W + SZ_W);
    const int k0 = blockIdx.x * 32, n0 = blockIdx.y * 32;
    const int tx = threadIdx.x, ty = threadIdx.y;
#pragma unroll
    for (int r = 0; r < 4; r++)
        t[ty + r * 8][tx] = W[(size_t)(k0 + ty + r * 8) * DIMN + n0 + tx];
    __syncthreads();
#pragma unroll
    for (int r = 0; r < 4; r++) {
        int n = n0 + ty + r * 8, k = k0 + tx;
        bf16 h, l;
        split2(t[tx][ty + r * 8], h, l);
        size_t o = (size_t)n * DIMN + k;
        Th[o] = h; Tl[o] = l;
    }
}

__global__ __launch_bounds__(256) void copy_bias(
    const float* __restrict__ b0, const float* __restrict__ b1,
    const float* __restrict__ b2, const float* __restrict__ b3)
{
    const int z = blockIdx.y;
    const float* src = (z == 0) ? b0 : (z == 1) ? b1 : (z == 2) ? b2 : b3;
    float* dst = (float*)(gArena + OFF_B) + (size_t)z * DIMN;
    int i = blockIdx.x * 256 + threadIdx.x;
    dst[i] = src[i];
}

__global__ __launch_bounds__(128) void norm_rope_cv(
    const float* __restrict__ nq, const float* __restrict__ nk,
    const float* __restrict__ cosb, const float* __restrict__ sinb)
{
    const float* Qf = (const float*)(gArena + OFF_Q);
    const float* Kf = (const float*)(gArena + OFF_K);
    bf16* Qh = (bf16*)(gArena + OFF_QH); bf16* Ql = (bf16*)(gArena + OFF_QL);
    bf16* Kh = (bf16*)(gArena + OFF_KH); bf16* Kl = (bf16*)(gArena + OFF_KL);

    const int s = blockIdx.x, h = blockIdx.y, d = threadIdx.x;
    const size_t idx = (size_t)s * DIMN + h * HD + d;
    float q = Qf[idx], k = Kf[idx];
    float sq = q * q, sk = k * k;
#pragma unroll
    for (int off = 16; off; off >>= 1) {
        sq += __shfl_xor_sync(0xffffffffu, sq, off);
        sk += __shfl_xor_sync(0xffffffffu, sk, off);
    }
    __shared__ float red[8];
    const int w = d >> 5;
    if ((d & 31) == 0) { red[w] = sq; red[4 + w] = sk; }
    __syncthreads();
    float tq = red[0] + red[1] + red[2] + red[3];
    float tk = red[4] + red[5] + red[6] + red[7];
    q *= rsqrtf(tq * (1.0f / HD) + EPSV) * nq[d];
    k *= rsqrtf(tk * (1.0f / HD) + EPSV) * nk[d];
    if (s < S_IMG) {
        float qo = __shfl_xor_sync(0xffffffffu, q, 1);
        float ko = __shfl_xor_sync(0xffffffffu, k, 1);
        float c = cosb[s * HD + d], sn = sinb[s * HD + d];
        float sgn = (d & 1) ? 1.0f : -1.0f;
        q = q * c + sgn * qo * sn;
        k = k * c + sgn * ko * sn;
    }
    q *= SM_SCALE;
    bf16 hh, ll;
    split2(q, hh, ll); Qh[idx] = hh; Ql[idx] = ll;
    split2(k, hh, ll); Kh[idx] = hh; Kl[idx] = ll;
}

__global__ __launch_bounds__(256) void v_transpose()
{
    const float* V = (const float*)(gArena + OFF_V);
    bf16* Th = (bf16*)(gArena + OFF_VTH);
    bf16* Tl = (bf16*)(gArena + OFF_VTL);
    __shared__ float t[32][33];
    const int s0 = blockIdx.x * 32, d0 = blockIdx.y * 32, h = blockIdx.z;
    const int tx = threadIdx.x, ty = threadIdx.y;
#pragma unroll
    for (int r = 0; r < 4; r++)
        t[ty + r * 8][tx] = V[(size_t)(s0 + ty + r * 8) * DIMN + h * HD + d0 + tx];
    __syncthreads();
#pragma unroll
    for (int r = 0; r < 4; r++) {
        int d = d0 + ty + r * 8, s = s0 + tx;
        bf16 hh, ll;
        split2(t[tx][ty + r * 8], hh, ll);
        size_t o = (size_t)h * HD * SEQ + (size_t)d * SEQ + s;
        Th[o] = hh; Tl[o] = ll;
    }
}

__global__ __launch_bounds__(256) void o_convert()
{
    const float* O = (const float*)(gArena + OFF_O);
    bf16* Oh = (bf16*)(gArena + OFF_OH);
    bf16* Ol = (bf16*)(gArena + OFF_OL);
    const size_t o = (size_t)blockIdx.x * DIMN;
#pragma unroll
    for (int j = 0; j < 12; j++) {
        int c = threadIdx.x + j * 256;
        bf16 h, l;
        split2(O[o + c], h, l);
        Oh[o + c] = h; Ol[o + c] = l;
    }
}

__global__ __launch_bounds__(256) void copy_txt(float* __restrict__ out)
{
    const float* O = (const float*)(gArena + OFF_O);
    size_t i = (size_t)blockIdx.x * 256 + threadIdx.x;
    out[(size_t)S_IMG * DIMN + i] = O[(size_t)S_IMG * DIMN + i];
}

// ================= launch ===================================================
extern "C" void kernel_launch(void* const* d_in, const int* in_sizes, int n_in,
                              void* d_out, int out_size)
{
    const float* hs  = (const float*)d_in[0];
    const float* enc = (const float*)d_in[1];
    const float* cs  = (const float*)d_in[2];
    const float* sn  = (const float*)d_in[3];
    const float* wq  = (const float*)d_in[4];
    const float* wk  = (const float*)d_in[6];
    const float* wv  = (const float*)d_in[8];
    const float* nqw = (const float*)d_in[10];
    const float* nkw = (const float*)d_in[11];
    const float* wo  = (const float*)d_in[12];
    float* out = (float*)d_out;
    (void)in_sizes; (void)n_in; (void)out_size;

    cudaFuncSetAttribute(gemm_bf16s,
                         cudaFuncAttributeMaxDynamicSharedMemorySize, GEMM_SMEM);
    cudaFuncSetAttribute(attn_fused,
                         cudaFuncAttributeMaxDynamicSharedMemorySize, ATTN_SMEM);

    const long long E_W = (long long)DIMN * DIMN;
    const long long E_F = (long long)SEQ * DIMN;

    // 1. input & weight preparation
    convert_x<<<SEQ, 256>>>(hs, enc);
    transpose_w<<<dim3(DIMN / 32, DIMN / 32, 4), dim3(32, 8)>>>(wq, wk, wv, wo);
    copy_bias<<<dim3(DIMN / 256, 4), 256>>>(
        (const float*)d_in[5], (const float*)d_in[7],
        (const float*)d_in[9], (const float*)d_in[13]);

    // 2. QKV projections, merged (M=2304, N=3072, K=3072)
    gemm_bf16s<<<dim3(24, 18, 3), GEMM_THREADS, GEMM_SMEM>>>(
        OFF_XH, OFF_XL, DIMN, 0,
        OFF_W, OFF_W + SZ_W, DIMN, 2 * E_W,
        OFF_Q, DIMN, E_F,
        OFF_B, DIMN, DIMN, nullptr);

    // 3. RMSNorm + RoPE + split-convert; V transpose
    norm_rope_cv<<<dim3(SEQ, HEADS), 128>>>(nqw, nkw, cs, sn);
    v_transpose<<<dim3(SEQ / 32, HD / 32, HEADS), dim3(32, 8)>>>();

    // 4. fused attention: S/softmax/PV all in one kernel, S stays on-chip
    attn_fused<<<dim3(SEQ / 128, HEADS), ATTN_THREADS, ATTN_SMEM>>>();

    // 5. output projection on img rows (M=2048, N=3072, K=3072) + txt copy
    o_convert<<<S_IMG, 256>>>();
    gemm_bf16s<<<dim3(24, 16, 1), GEMM_THREADS, GEMM_SMEM>>>(
        OFF_OH, OFF_OL, DIMN, 0,
        OFF_W + 6 * SZ_W, OFF_W + 7 * SZ_W, DIMN, 0,
        0, DIMN, 0,
        OFF_B + 3LL * DIMN * 4, 0, DIMN, out);
    copy_txt<<<(S_TXT * DIMN) / 256, 256>>>(out);
}